// round 12
// baseline (speedup 1.0000x reference)
#include <cuda_runtime.h>
#include <cuda_fp16.h>

#define BATCH 8
#define CCH   128
#define NTOK  16384
#define HEADS 8
#define LN_EPS 1e-5f

// ---------------- device scratch ----------------
__device__ float  g_kv[BATCH * HEADS * 16 * 16];
__device__ __half g_wkv[256 * 128];
__device__ __half g_o1h[128 * 128];
__device__ __half g_o2h[128 * 128];
__device__ __half g_m1[BATCH * 128 * 128];     // composed o1*(Meff+I), per batch
__device__ float  g_bias1[BATCH * 128];        // o1*meffb + o1_b
__device__ __half g_x16[(size_t)BATCH * CCH * NTOK];

// ---------------- helpers ----------------
__device__ __forceinline__ unsigned pk2h(float a, float b) {
    __half2 h = __floats2half2_rn(a, b);
    return *reinterpret_cast<unsigned*>(&h);
}

__device__ __forceinline__ void mma16816h(float* c, const unsigned* a, const unsigned* b) {
    asm volatile(
        "mma.sync.aligned.m16n8k16.row.col.f32.f16.f16.f32 "
        "{%0,%1,%2,%3}, {%4,%5,%6,%7}, {%8,%9}, {%0,%1,%2,%3};\n"
        : "+f"(c[0]), "+f"(c[1]), "+f"(c[2]), "+f"(c[3])
        : "r"(a[0]), "r"(a[1]), "r"(a[2]), "r"(a[3]), "r"(b[0]), "r"(b[1]));
}

__device__ __forceinline__ unsigned smem_u32(const void* p) {
    return (unsigned)__cvta_generic_to_shared(p);
}

__device__ __forceinline__ void ldsm4(unsigned& r0, unsigned& r1, unsigned& r2, unsigned& r3,
                                      unsigned addr) {
    asm volatile("ldmatrix.sync.aligned.m8n8.x4.shared.b16 {%0,%1,%2,%3}, [%4];\n"
                 : "=r"(r0), "=r"(r1), "=r"(r2), "=r"(r3) : "r"(addr));
}

__device__ __forceinline__ void ldsm4t(unsigned& r0, unsigned& r1, unsigned& r2, unsigned& r3,
                                       unsigned addr) {
    asm volatile("ldmatrix.sync.aligned.m8n8.x4.trans.shared.b16 {%0,%1,%2,%3}, [%4];\n"
                 : "=r"(r0), "=r"(r1), "=r"(r2), "=r"(r3) : "r"(addr));
}

__device__ __forceinline__ void cpasync16(unsigned s, const void* g) {
    asm volatile("cp.async.cg.shared.global [%0], [%1], 16;\n" :: "r"(s), "l"(g));
}
#define CP_COMMIT() asm volatile("cp.async.commit_group;\n")
#define CP_WAIT(n)  asm volatile("cp.async.wait_group %0;\n" :: "n"(n))

__device__ __forceinline__ float rsqrt_fast(float x) {
    float r;
    asm("rsqrt.approx.f32 %0, %1;\n" : "=f"(r) : "f"(x));
    return r;
}

// fast erf: Abramowitz-Stegun 7.1.26
__device__ __forceinline__ float fast_erf(float x) {
    float ax = fabsf(x);
    float t = __fdividef(1.f, fmaf(0.3275911f, ax, 1.f));
    float p = fmaf(1.061405429f, t, -1.453152027f);
    p = fmaf(p, t, 1.421413741f);
    p = fmaf(p, t, -0.284496736f);
    p = fmaf(p, t, 0.254829592f);
    p *= t;
    float r = 1.f - p * __expf(-ax * ax);
    return copysignf(r, x);
}

// Output-layout GEMM: C[c_out rows][token cols] = A[c_out][k=128] * B[k=128][t].
template <int NI8, int LDB>
__device__ __forceinline__ void gemm_t(const __half* __restrict__ A,
                                       const __half* __restrict__ B,
                                       float (&acc)[2][NI8][4], int rbase, int cbase, int lane) {
    unsigned a_addr = smem_u32(A + (rbase + (lane & 15)) * 136 + ((lane >> 4) << 3));
    unsigned b_addr = smem_u32(B + (lane & 15) * LDB + cbase + ((lane >> 4) << 3));
#pragma unroll
    for (int kc = 0; kc < 128; kc += 16) {
        unsigned a[2][4];
        ldsm4(a[0][0], a[0][1], a[0][2], a[0][3], a_addr);
        ldsm4(a[1][0], a[1][1], a[1][2], a[1][3], a_addr + 16 * 136 * 2);
#pragma unroll
        for (int g = 0; g < NI8 / 2; g++) {
            unsigned b0, b1, b2, b3;
            ldsm4t(b0, b1, b2, b3, b_addr + g * 32);
            unsigned bl[2] = {b0, b1}, bh[2] = {b2, b3};
            mma16816h(acc[0][2 * g],     a[0], bl);
            mma16816h(acc[1][2 * g],     a[1], bl);
            mma16816h(acc[0][2 * g + 1], a[0], bh);
            mma16816h(acc[1][2 * g + 1], a[1], bh);
        }
        a_addr += 32;
        b_addr += 16 * LDB * 2;
    }
}

// ---------------- kernel 0: weight prep ----------------
__global__ void prep_kernel(const float* __restrict__ qkv_w,
                            const float* __restrict__ o1_w,
                            const float* __restrict__ o2_w) {
    int idx = blockIdx.x * blockDim.x + threadIdx.x;
    int nthr = gridDim.x * blockDim.x;
    for (int i = idx; i < BATCH * HEADS * 16 * 16; i += nthr) g_kv[i] = 0.f;
    for (int i = idx; i < 256 * 128; i += nthr) {
        int r = i >> 7, c = i & 127;
        int h = r >> 5, j = r & 31;
        int src = (j < 16) ? (48 * h + 16 + j) : (48 * h + 32 + (j - 16));
        g_wkv[i] = __float2half_rn(qkv_w[src * 128 + c]);
    }
    for (int i = idx; i < 128 * 128; i += nthr) {
        g_o1h[i] = __float2half_rn(o1_w[i]);
        g_o2h[i] = __float2half_rn(o2_w[i]);
    }
}

// ---------------- kernel 1: x->fp16 + k,v projection + register-LN + register-kv MMA ----------------
#define KVS_WT    0
#define KVS_XT0   (256 * 136 * 2)
#define KVS_XT1   (KVS_XT0 + 128 * 136 * 2)
#define KVS_STAGE (KVS_XT1 + 128 * 136 * 2)
#define KVS_QB    (KVS_STAGE + 128 * 128 * 4)
#define KVS_SMEM  (KVS_QB + 256 * 4)

__global__ void __launch_bounds__(512, 1) kv_kernel(const float* __restrict__ x,
                                                    const float* __restrict__ qkv_b,
                                                    const float* __restrict__ kln_w,
                                                    const float* __restrict__ kln_b,
                                                    const float* __restrict__ vln_w,
                                                    const float* __restrict__ vln_b) {
    extern __shared__ char smem[];
    __half* Wt = (__half*)(smem + KVS_WT);
    __half* xt0 = (__half*)(smem + KVS_XT0);
    __half* xt1 = (__half*)(smem + KVS_XT1);
    float* stg = (float*)(smem + KVS_STAGE);
    float* qb = (float*)(smem + KVS_QB);

    int tid = threadIdx.x;
    int b = blockIdx.y;
    const float* xb = x + (size_t)b * CCH * NTOK;
    __half* x16b = g_x16 + (size_t)b * CCH * NTOK;
    int n0base = blockIdx.x * 256;

    {
        unsigned wt = smem_u32(Wt);
        for (int i = tid; i < 256 * 16; i += 512) {
            int r = i >> 4, c = i & 15;
            cpasync16(wt + r * 272 + c * 16, g_wkv + r * 128 + c * 8);
        }
        unsigned sa = smem_u32(stg);
        for (int i = tid; i < 128 * 32; i += 512) {
            int r = i >> 5, c = i & 31;
            cpasync16(sa + r * 512 + c * 16, xb + (size_t)r * NTOK + n0base + c * 4);
        }
        CP_COMMIT();
    }
    if (tid < 256) {
        int h = tid >> 5, j = tid & 31;
        int src_r = (j < 16) ? (48 * h + 16 + j) : (48 * h + 32 + (j - 16));
        qb[tid] = qkv_b[src_r];
    }

    int w = tid >> 5, l = tid & 31;
    int lr = l >> 2, lc = l & 3;
    int mw = w >> 1;
    int nw = w & 1;
    int rbase = mw * 32, cbase = nw * 64;

    float lw[2][2], lb[2][2];
    lw[0][0] = kln_w[mw * 16 + lr];     lw[0][1] = kln_w[mw * 16 + lr + 8];
    lb[0][0] = kln_b[mw * 16 + lr];     lb[0][1] = kln_b[mw * 16 + lr + 8];
    lw[1][0] = vln_w[mw * 16 + lr];     lw[1][1] = vln_w[mw * 16 + lr + 8];
    lb[1][0] = vln_b[mw * 16 + lr];     lb[1][1] = vln_b[mw * 16 + lr + 8];

    float acc2[2][4];
#pragma unroll
    for (int e = 0; e < 2; e++)
#pragma unroll
        for (int q = 0; q < 4; q++) acc2[e][q] = 0.f;

#pragma unroll
    for (int tile = 0; tile < 2; tile++) {
        int n0 = n0base + tile * 128;
        __half* xt = tile ? xt1 : xt0;

        CP_WAIT(0);
        __syncthreads();

#pragma unroll
        for (int k = 0; k < 8; k++) {
            int i = tid + k * 512;
            int r = i >> 5, c4 = i & 31;
            float4 v = *(const float4*)(stg + r * 128 + c4 * 4);
            __half2 h0 = __floats2half2_rn(v.x, v.y);
            __half2 h1 = __floats2half2_rn(v.z, v.w);
            uint2 u;
            u.x = *reinterpret_cast<unsigned*>(&h0);
            u.y = *reinterpret_cast<unsigned*>(&h1);
            *(uint2*)(xt + r * 136 + c4 * 4) = u;
            *(uint2*)(x16b + (size_t)r * NTOK + n0 + c4 * 4) = u;
        }
        __syncthreads();

        if (tile == 0) {
            unsigned sa = smem_u32(stg);
            for (int i = tid; i < 128 * 32; i += 512) {
                int r = i >> 5, c = i & 31;
                cpasync16(sa + r * 512 + c * 16, xb + (size_t)r * NTOK + n0base + 128 + c * 4);
            }
            CP_COMMIT();
        }

        float acc[2][8][4];
#pragma unroll
        for (int a_ = 0; a_ < 2; a_++)
#pragma unroll
            for (int b_ = 0; b_ < 8; b_++)
#pragma unroll
                for (int c_ = 0; c_ < 4; c_++) acc[a_][b_][c_] = 0.f;

        gemm_t<8, 136>(Wt, xt, acc, rbase, cbase, l);

        float q0 = qb[rbase + lr],      q1 = qb[rbase + lr + 8];
        float q2 = qb[rbase + 16 + lr], q3 = qb[rbase + 16 + lr + 8];
#pragma unroll
        for (int ni = 0; ni < 8; ni++) {
            acc[0][ni][0] += q0; acc[0][ni][1] += q0;
            acc[0][ni][2] += q1; acc[0][ni][3] += q1;
            acc[1][ni][0] += q2; acc[1][ni][1] += q2;
            acc[1][ni][2] += q3; acc[1][ni][3] += q3;
        }

        unsigned kf[8][2], vf[8][2];
#pragma unroll
        for (int mi = 0; mi < 2; mi++) {
#pragma unroll
            for (int ni = 0; ni < 8; ni++) {
                float* c = acc[mi][ni];
                __half2 s2 = __floats2half2_rn(c[0] + c[2], c[1] + c[3]);
                __half2 q2h = __floats2half2_rn(fmaf(c[0], c[0], c[2] * c[2]),
                                                fmaf(c[1], c[1], c[3] * c[3]));
                unsigned su = *reinterpret_cast<unsigned*>(&s2);
                unsigned qu = *reinterpret_cast<unsigned*>(&q2h);
#pragma unroll
                for (int m = 4; m <= 16; m <<= 1) {
                    unsigned so = __shfl_xor_sync(0xffffffffu, su, m);
                    unsigned qo = __shfl_xor_sync(0xffffffffu, qu, m);
                    __half2 rs2 = __hadd2(*reinterpret_cast<__half2*>(&su),
                                          *reinterpret_cast<__half2*>(&so));
                    __half2 rq2 = __hadd2(*reinterpret_cast<__half2*>(&qu),
                                          *reinterpret_cast<__half2*>(&qo));
                    su = *reinterpret_cast<unsigned*>(&rs2);
                    qu = *reinterpret_cast<unsigned*>(&rq2);
                }
                float2 s = __half22float2(*reinterpret_cast<__half2*>(&su));
                float2 q = __half22float2(*reinterpret_cast<__half2*>(&qu));
                float ma = s.x * (1.f / 16.f);
                float va = fmaxf((q.x - 16.f * ma * ma) * (1.f / 15.f), 1e-12f);
                float rsa = rsqrt_fast(va);
                float ia = fmaf(-LN_EPS * rsa, rsa, rsa);
                float mb = s.y * (1.f / 16.f);
                float vb = fmaxf((q.y - 16.f * mb * mb) * (1.f / 15.f), 1e-12f);
                float rsb = rsqrt_fast(vb);
                float ib = fmaf(-LN_EPS * rsb, rsb, rsb);
                float n0v = lw[mi][0] * ((c[0] - ma) * ia) + lb[mi][0];
                float n1v = lw[mi][0] * ((c[1] - mb) * ib) + lb[mi][0];
                float n2v = lw[mi][1] * ((c[2] - ma) * ia) + lb[mi][1];
                float n3v = lw[mi][1] * ((c[3] - mb) * ib) + lb[mi][1];
                unsigned lo = pk2h(n0v, n1v);
                unsigned hi = pk2h(n2v, n3v);
                if (mi == 0) { kf[ni][0] = lo; kf[ni][1] = hi; }
                else         { vf[ni][0] = lo; vf[ni][1] = hi; }
            }
        }

#pragma unroll
        for (int tc = 0; tc < 4; tc++) {
            unsigned a[4] = {kf[2 * tc][0], kf[2 * tc][1], kf[2 * tc + 1][0], kf[2 * tc + 1][1]};
            unsigned b0[2] = {vf[2 * tc][0], vf[2 * tc + 1][0]};
            unsigned b1[2] = {vf[2 * tc][1], vf[2 * tc + 1][1]};
            mma16816h(acc2[0], a, b0);
            mma16816h(acc2[1], a, b1);
        }
    }

    float* base = g_kv + (size_t)(b * HEADS + mw) * 256;
#pragma unroll
    for (int eh = 0; eh < 2; eh++) {
        int e0 = eh * 8 + lc * 2;
        atomicAdd(base + lr * 16 + e0,           acc2[eh][0]);
        atomicAdd(base + lr * 16 + e0 + 1,       acc2[eh][1]);
        atomicAdd(base + (lr + 8) * 16 + e0,     acc2[eh][2]);
        atomicAdd(base + (lr + 8) * 16 + e0 + 1, acc2[eh][3]);
    }
}

// ---------------- kernel 2: compose M1_b = o1*(Meff_b + I), bias1_b = o1*meffb + o1_b ----------------
// One block per batch, 512 threads.
#define CMP_KVS  0
#define CMP_MB   (HEADS * 256 * 4)
#define CMP_MI   (CMP_MB + 128 * 4)
#define CMP_O1   (CMP_MI + 128 * 136 * 2)
#define CMP_SMEM (CMP_O1 + 128 * 136 * 2)

__global__ void __launch_bounds__(512, 1) compose_kernel(const float* __restrict__ qkv_w,
                                                         const float* __restrict__ qkv_b,
                                                         const float* __restrict__ o1_b) {
    extern __shared__ char smem[];
    float* kvs = (float*)(smem + CMP_KVS);          // [8 heads][16 d][16 e]
    float* mb = (float*)(smem + CMP_MB);            // meffb[128]
    __half* mi = (__half*)(smem + CMP_MI);          // (Meff+I) [co][ci], ld 136
    __half* o1s = (__half*)(smem + CMP_O1);         // o1 [i][k], ld 136

    int b = blockIdx.x;
    int tid = threadIdx.x;

    // prefetch o1
    {
        unsigned oa = smem_u32(o1s);
        for (int i = tid; i < 128 * 16; i += 512) {
            int r = i >> 4, c = i & 15;
            cpasync16(oa + r * 272 + c * 16, g_o1h + r * 128 + c * 8);
        }
        CP_COMMIT();
    }
    for (int i = tid; i < HEADS * 256; i += 512)
        kvs[i] = g_kv[b * HEADS * 256 + i] * (1.f / (float)NTOK);
    __syncthreads();

    // meffb[co] = sum_d qkv_b[48h+d] * kv[h][d][e],  co = h*16+e
    if (tid < 128) {
        int h = tid >> 4, e = tid & 15;
        float s = 0.f;
#pragma unroll
        for (int d = 0; d < 16; d++) s += qkv_b[48 * h + d] * kvs[h * 256 + d * 16 + e];
        mb[tid] = s;
    }

    // Meff + I -> mi (fp16). thread (cog, ci) handles heads 2cog..2cog+1.
    {
        int ci = tid & 127;
        int cog = tid >> 7;
#pragma unroll
        for (int hh = 0; hh < 2; hh++) {
            int h = cog * 2 + hh;
            float wq[16];
#pragma unroll
            for (int d = 0; d < 16; d++) wq[d] = qkv_w[(48 * h + d) * 128 + ci];
#pragma unroll
            for (int e = 0; e < 16; e++) {
                float s = 0.f;
#pragma unroll
                for (int d = 0; d < 16; d++) s += wq[d] * kvs[h * 256 + d * 16 + e];
                int co = h * 16 + e;
                if (co == ci) s += 1.f;
                mi[co * 136 + ci] = __float2half_rn(s);
            }
        }
    }
    CP_WAIT(0);
    __syncthreads();

    // M1 = o1s (A) x mi (B, trans): C[i rows][ci cols]
    int w = tid >> 5, l = tid & 31;
    int lr = l >> 2, lc = l & 3;
    int mw = w >> 2, nw = w & 3;
    int rbase = mw * 32, cbase = nw * 32;

    float acc[2][4][4];
#pragma unroll
    for (int a_ = 0; a_ < 2; a_++)
#pragma unroll
        for (int b_ = 0; b_ < 4; b_++)
#pragma unroll
            for (int c_ = 0; c_ < 4; c_++) acc[a_][b_][c_] = 0.f;

    gemm_t<4, 136>(o1s, mi, acc, rbase, cbase, l);

    __half* mdst = g_m1 + (size_t)b * 128 * 128;
#pragma unroll
    for (int mi_ = 0; mi_ < 2; mi_++) {
        int row = rbase + mi_ * 16 + lr;
#pragma unroll
        for (int ni = 0; ni < 4; ni++) {
            int col = cbase + ni * 8 + lc * 2;
            *(unsigned*)(mdst + row * 128 + col)       = pk2h(acc[mi_][ni][0], acc[mi_][ni][1]);
            *(unsigned*)(mdst + (row + 8) * 128 + col) = pk2h(acc[mi_][ni][2], acc[mi_][ni][3]);
        }
    }

    // bias1[i] = sum_k o1[i][k]*meffb[k] + o1_b[i]
    if (tid < 128) {
        float s = o1_b[tid];
#pragma unroll 16
        for (int k = 0; k < 128; k++)
            s += __half2float(o1s[tid * 136 + k]) * mb[k];
        g_bias1[b * 128 + tid] = s;
    }
}

// ---------------- kernel 3: fused [gelu(M1*x + bias1)] -> [o2*h1 + b2 + x] ----------------
#define M4_LDB  264
#define M4_XT   0
#define M4_RT   (128 * M4_LDB * 2)
#define M4_WA   (2 * 128 * M4_LDB * 2)
#define M4_WB   (M4_WA + 128 * 136 * 2)
#define M4_BIAS (M4_WB + 128 * 136 * 2)
#define M4_SMEM (M4_BIAS + 2 * 128 * 4)

__global__ void __launch_bounds__(512, 1) main_kernel(const float* __restrict__ o2_b,
                                                      float* __restrict__ out) {
    extern __shared__ char smem[];
    __half* xt = (__half*)(smem + M4_XT);
    __half* rt = (__half*)(smem + M4_RT);
    __half* wA = (__half*)(smem + M4_WA);    // M1
    __half* wB = (__half*)(smem + M4_WB);    // o2
    float* bias = (float*)(smem + M4_BIAS);

    int tid = threadIdx.x;
    int b = blockIdx.y;
    int n0 = blockIdx.x * 256;

    {
        unsigned wa = smem_u32(wA), xa = smem_u32(xt);
        const __half* msrc = g_m1 + (size_t)b * 128 * 128;
        const __half* xsrc = g_x16 + (size_t)b * CCH * NTOK + n0;
        for (int i = tid; i < 128 * 16; i += 512) {
            int r = i >> 4, c = i & 15;
            cpasync16(wa + r * 272 + c * 16, msrc + r * 128 + c * 8);
        }
        for (int i = tid; i < 128 * 32; i += 512) {
            int r = i >> 5, c = i & 31;
            cpasync16(xa + r * (M4_LDB * 2) + c * 16, xsrc + (size_t)r * NTOK + c * 8);
        }
        CP_COMMIT();
        unsigned wb = smem_u32(wB);
        for (int i = tid; i < 128 * 16; i += 512) {
            int r = i >> 4, c = i & 15;
            cpasync16(wb + r * 272 + c * 16, g_o2h + r * 128 + c * 8);
        }
        CP_COMMIT();
    }
    if (tid < 128) {
        bias[tid] = g_bias1[b * 128 + tid];
        bias[128 + tid] = o2_b[tid];
    }
    CP_WAIT(1);
    __syncthreads();

    int w = tid >> 5, l = tid & 31;
    int lr = l >> 2, lc = l & 3;
    int mw = w >> 2, nw = w & 3;
    int rbase = mw * 32, cbase = nw * 64;

    float acc[2][8][4];
#define ZACC() { _Pragma("unroll") for (int a_=0;a_<2;a_++) _Pragma("unroll") for (int b_=0;b_<8;b_++) _Pragma("unroll") for (int c_=0;c_<4;c_++) acc[a_][b_][c_]=0.f; }

    // ---- phase 1: h1 = gelu(M1*x + bias1) ----
    ZACC();
    gemm_t<8, M4_LDB>(wA, xt, acc, rbase, cbase, l);
    {
        float b10 = bias[rbase + lr],      b11 = bias[rbase + lr + 8];
        float b12 = bias[rbase + 16 + lr], b13 = bias[rbase + 16 + lr + 8];
#pragma unroll
        for (int mi = 0; mi < 2; mi++) {
            int row = rbase + mi * 16 + lr;
            float ba0 = mi ? b12 : b10, ba1 = mi ? b13 : b11;
#pragma unroll
            for (int ni = 0; ni < 8; ni++) {
                int col = cbase + ni * 8 + lc * 2;
                float h0 = acc[mi][ni][0] + ba0;
                float h1 = acc[mi][ni][1] + ba0;
                float h2 = acc[mi][ni][2] + ba1;
                float h3 = acc[mi][ni][3] + ba1;
                h0 = 0.5f * h0 * (1.f + fast_erf(h0 * 0.70710678118654752f));
                h1 = 0.5f * h1 * (1.f + fast_erf(h1 * 0.70710678118654752f));
                h2 = 0.5f * h2 * (1.f + fast_erf(h2 * 0.70710678118654752f));
                h3 = 0.5f * h3 * (1.f + fast_erf(h3 * 0.70710678118654752f));
                *(unsigned*)(rt + row * M4_LDB + col)       = pk2h(h0, h1);
                *(unsigned*)(rt + (row + 8) * M4_LDB + col) = pk2h(h2, h3);
            }
        }
    }
    CP_WAIT(0);
    __syncthreads();  // rt complete; o2 in wB

    // ---- phase 2: out = o2 * h1 + b2 + x ----
    ZACC();
    gemm_t<8, M4_LDB>(wB, rt, acc, rbase, cbase, l);
    {
        float b20 = bias[128 + rbase + lr],      b21 = bias[128 + rbase + lr + 8];
        float b22 = bias[128 + rbase + 16 + lr], b23 = bias[128 + rbase + 16 + lr + 8];
        float* ob = out + (size_t)b * CCH * NTOK + n0;
#pragma unroll
        for (int mi = 0; mi < 2; mi++) {
            int row = rbase + mi * 16 + lr;
            float ba0 = mi ? b22 : b20, ba1 = mi ? b23 : b21;
#pragma unroll
            for (int ni = 0; ni < 8; ni++) {
                int col = cbase + ni * 8 + lc * 2;
                __half2 xv0 = *(const __half2*)(xt + row * M4_LDB + col);
                __half2 xv1 = *(const __half2*)(xt + (row + 8) * M4_LDB + col);
                float2 f0 = __half22float2(xv0), f1 = __half22float2(xv1);
                float2 o0, o1v;
                o0.x = acc[mi][ni][0] + ba0 + f0.x;
                o0.y = acc[mi][ni][1] + ba0 + f0.y;
                o1v.x = acc[mi][ni][2] + ba1 + f1.x;
                o1v.y = acc[mi][ni][3] + ba1 + f1.y;
                __stcs((float2*)(ob + (size_t)row * NTOK + col), o0);
                __stcs((float2*)(ob + (size_t)(row + 8) * NTOK + col), o1v);
            }
        }
    }
}

// ---------------- launch ----------------
extern "C" void kernel_launch(void* const* d_in, const int* in_sizes, int n_in,
                              void* d_out, int out_size) {
    const float* x     = (const float*)d_in[0];
    const float* qkv_w = (const float*)d_in[1];
    const float* qkv_b = (const float*)d_in[2];
    const float* o1_w  = (const float*)d_in[3];
    const float* o1_b  = (const float*)d_in[4];
    const float* o2_w  = (const float*)d_in[5];
    const float* o2_b  = (const float*)d_in[6];
    const float* kln_w = (const float*)d_in[7];
    const float* kln_b = (const float*)d_in[8];
    const float* vln_w = (const float*)d_in[9];
    const float* vln_b = (const float*)d_in[10];
    float* out = (float*)d_out;

    cudaFuncSetAttribute(kv_kernel, cudaFuncAttributeMaxDynamicSharedMemorySize, KVS_SMEM);
    cudaFuncSetAttribute(compose_kernel, cudaFuncAttributeMaxDynamicSharedMemorySize, CMP_SMEM);
    cudaFuncSetAttribute(main_kernel, cudaFuncAttributeMaxDynamicSharedMemorySize, M4_SMEM);

    prep_kernel<<<128, 256>>>(qkv_w, o1_w, o2_w);

    dim3 g2(NTOK / 256, BATCH);
    kv_kernel<<<g2, 512, KVS_SMEM>>>(x, qkv_b, kln_w, kln_b, vln_w, vln_b);

    compose_kernel<<<BATCH, 512, CMP_SMEM>>>(qkv_w, qkv_b, o1_b);

    dim3 g4(NTOK / 256, BATCH);
    main_kernel<<<g4, 512, M4_SMEM>>>(o2_b, out);
}

// round 13
// speedup vs baseline: 1.3745x; 1.3745x over previous
#include <cuda_runtime.h>
#include <cuda_fp16.h>

#define BATCH 8
#define CCH   128
#define NTOK  16384
#define HEADS 8
#define LN_EPS 1e-5f

// ---------------- device scratch ----------------
__device__ float  g_kv[BATCH * HEADS * 16 * 16];
__device__ __half g_wkv[256 * 128];
__device__ __half g_o1h[128 * 128];
__device__ __half g_o2h[128 * 128];
__device__ __half g_meff[BATCH * 128 * 128];
__device__ float  g_meffb[BATCH * 128];
__device__ __half g_x16[(size_t)BATCH * CCH * NTOK];

// ---------------- helpers ----------------
__device__ __forceinline__ unsigned pk2h(float a, float b) {
    __half2 h = __floats2half2_rn(a, b);
    return *reinterpret_cast<unsigned*>(&h);
}

__device__ __forceinline__ void mma16816h(float* c, const unsigned* a, const unsigned* b) {
    asm volatile(
        "mma.sync.aligned.m16n8k16.row.col.f32.f16.f16.f32 "
        "{%0,%1,%2,%3}, {%4,%5,%6,%7}, {%8,%9}, {%0,%1,%2,%3};\n"
        : "+f"(c[0]), "+f"(c[1]), "+f"(c[2]), "+f"(c[3])
        : "r"(a[0]), "r"(a[1]), "r"(a[2]), "r"(a[3]), "r"(b[0]), "r"(b[1]));
}

__device__ __forceinline__ unsigned smem_u32(const void* p) {
    return (unsigned)__cvta_generic_to_shared(p);
}

__device__ __forceinline__ void ldsm4(unsigned& r0, unsigned& r1, unsigned& r2, unsigned& r3,
                                      unsigned addr) {
    asm volatile("ldmatrix.sync.aligned.m8n8.x4.shared.b16 {%0,%1,%2,%3}, [%4];\n"
                 : "=r"(r0), "=r"(r1), "=r"(r2), "=r"(r3) : "r"(addr));
}

__device__ __forceinline__ void ldsm4t(unsigned& r0, unsigned& r1, unsigned& r2, unsigned& r3,
                                       unsigned addr) {
    asm volatile("ldmatrix.sync.aligned.m8n8.x4.trans.shared.b16 {%0,%1,%2,%3}, [%4];\n"
                 : "=r"(r0), "=r"(r1), "=r"(r2), "=r"(r3) : "r"(addr));
}

__device__ __forceinline__ void cpasync16(unsigned s, const void* g) {
    asm volatile("cp.async.cg.shared.global [%0], [%1], 16;\n" :: "r"(s), "l"(g));
}
#define CP_COMMIT() asm volatile("cp.async.commit_group;\n")
#define CP_WAIT(n)  asm volatile("cp.async.wait_group %0;\n" :: "n"(n))

__device__ __forceinline__ void stg_cs_u2(void* p, uint2 u) {
    asm volatile("st.global.cs.v2.b32 [%0], {%1, %2};\n" :: "l"(p), "r"(u.x), "r"(u.y));
}

__device__ __forceinline__ float rsqrt_fast(float x) {
    float r;
    asm("rsqrt.approx.f32 %0, %1;\n" : "=f"(r) : "f"(x));
    return r;
}

// fast erf: Abramowitz-Stegun 7.1.26
__device__ __forceinline__ float fast_erf(float x) {
    float ax = fabsf(x);
    float t = __fdividef(1.f, fmaf(0.3275911f, ax, 1.f));
    float p = fmaf(1.061405429f, t, -1.453152027f);
    p = fmaf(p, t, 1.421413741f);
    p = fmaf(p, t, -0.284496736f);
    p = fmaf(p, t, 0.254829592f);
    p *= t;
    float r = 1.f - p * __expf(-ax * ax);
    return copysignf(r, x);
}

// Output-layout GEMM: C[c_out rows][token cols] = A[c_out][k=128] * B[k=128][t].
template <int NI8, int LDB>
__device__ __forceinline__ void gemm_t(const __half* __restrict__ A,
                                       const __half* __restrict__ B,
                                       float (&acc)[2][NI8][4], int rbase, int cbase, int lane) {
    unsigned a_addr = smem_u32(A + (rbase + (lane & 15)) * 136 + ((lane >> 4) << 3));
    unsigned b_addr = smem_u32(B + (lane & 15) * LDB + cbase + ((lane >> 4) << 3));
#pragma unroll
    for (int kc = 0; kc < 128; kc += 16) {
        unsigned a[2][4];
        ldsm4(a[0][0], a[0][1], a[0][2], a[0][3], a_addr);
        ldsm4(a[1][0], a[1][1], a[1][2], a[1][3], a_addr + 16 * 136 * 2);
#pragma unroll
        for (int g = 0; g < NI8 / 2; g++) {
            unsigned b0, b1, b2, b3;
            ldsm4t(b0, b1, b2, b3, b_addr + g * 32);
            unsigned bl[2] = {b0, b1}, bh[2] = {b2, b3};
            mma16816h(acc[0][2 * g],     a[0], bl);
            mma16816h(acc[1][2 * g],     a[1], bl);
            mma16816h(acc[0][2 * g + 1], a[0], bh);
            mma16816h(acc[1][2 * g + 1], a[1], bh);
        }
        a_addr += 32;
        b_addr += 16 * LDB * 2;
    }
}

// ---------------- kernel 0: weight prep ----------------
__global__ void prep_kernel(const float* __restrict__ qkv_w,
                            const float* __restrict__ o1_w,
                            const float* __restrict__ o2_w) {
    int idx = blockIdx.x * blockDim.x + threadIdx.x;
    int nthr = gridDim.x * blockDim.x;
    for (int i = idx; i < BATCH * HEADS * 16 * 16; i += nthr) g_kv[i] = 0.f;
    for (int i = idx; i < 256 * 128; i += nthr) {
        int r = i >> 7, c = i & 127;
        int h = r >> 5, j = r & 31;
        int src = (j < 16) ? (48 * h + 16 + j) : (48 * h + 32 + (j - 16));
        g_wkv[i] = __float2half_rn(qkv_w[src * 128 + c]);
    }
    for (int i = idx; i < 128 * 128; i += nthr) {
        g_o1h[i] = __float2half_rn(o1_w[i]);
        g_o2h[i] = __float2half_rn(o2_w[i]);
    }
}

// ---------------- kernel 1: x->fp16 + k,v projection + register-LN + register-kv MMA ----------------
#define KVS_WT    0
#define KVS_XT0   (256 * 136 * 2)
#define KVS_XT1   (KVS_XT0 + 128 * 136 * 2)
#define KVS_STAGE (KVS_XT1 + 128 * 136 * 2)
#define KVS_QB    (KVS_STAGE + 128 * 128 * 4)
#define KVS_SMEM  (KVS_QB + 256 * 4)

__global__ void __launch_bounds__(512, 1) kv_kernel(const float* __restrict__ x,
                                                    const float* __restrict__ qkv_b,
                                                    const float* __restrict__ kln_w,
                                                    const float* __restrict__ kln_b,
                                                    const float* __restrict__ vln_w,
                                                    const float* __restrict__ vln_b) {
    extern __shared__ char smem[];
    __half* Wt = (__half*)(smem + KVS_WT);
    __half* xt0 = (__half*)(smem + KVS_XT0);
    __half* xt1 = (__half*)(smem + KVS_XT1);
    float* stg = (float*)(smem + KVS_STAGE);
    float* qb = (float*)(smem + KVS_QB);

    int tid = threadIdx.x;
    int b = blockIdx.y;
    const float* xb = x + (size_t)b * CCH * NTOK;
    __half* x16b = g_x16 + (size_t)b * CCH * NTOK;
    int n0base = blockIdx.x * 256;

    {
        unsigned wt = smem_u32(Wt);
        for (int i = tid; i < 256 * 16; i += 512) {
            int r = i >> 4, c = i & 15;
            cpasync16(wt + r * 272 + c * 16, g_wkv + r * 128 + c * 8);
        }
        unsigned sa = smem_u32(stg);
        for (int i = tid; i < 128 * 32; i += 512) {
            int r = i >> 5, c = i & 31;
            cpasync16(sa + r * 512 + c * 16, xb + (size_t)r * NTOK + n0base + c * 4);
        }
        CP_COMMIT();
    }
    if (tid < 256) {
        int h = tid >> 5, j = tid & 31;
        int src_r = (j < 16) ? (48 * h + 16 + j) : (48 * h + 32 + (j - 16));
        qb[tid] = qkv_b[src_r];
    }

    int w = tid >> 5, l = tid & 31;
    int lr = l >> 2, lc = l & 3;
    int mw = w >> 1;
    int nw = w & 1;
    int rbase = mw * 32, cbase = nw * 64;

    float lw[2][2], lb[2][2];
    lw[0][0] = kln_w[mw * 16 + lr];     lw[0][1] = kln_w[mw * 16 + lr + 8];
    lb[0][0] = kln_b[mw * 16 + lr];     lb[0][1] = kln_b[mw * 16 + lr + 8];
    lw[1][0] = vln_w[mw * 16 + lr];     lw[1][1] = vln_w[mw * 16 + lr + 8];
    lb[1][0] = vln_b[mw * 16 + lr];     lb[1][1] = vln_b[mw * 16 + lr + 8];

    float acc2[2][4];
#pragma unroll
    for (int e = 0; e < 2; e++)
#pragma unroll
        for (int q = 0; q < 4; q++) acc2[e][q] = 0.f;

#pragma unroll
    for (int tile = 0; tile < 2; tile++) {
        int n0 = n0base + tile * 128;
        __half* xt = tile ? xt1 : xt0;

        CP_WAIT(0);
        __syncthreads();

#pragma unroll
        for (int k = 0; k < 8; k++) {
            int i = tid + k * 512;
            int r = i >> 5, c4 = i & 31;
            float4 v = *(const float4*)(stg + r * 128 + c4 * 4);
            __half2 h0 = __floats2half2_rn(v.x, v.y);
            __half2 h1 = __floats2half2_rn(v.z, v.w);
            uint2 u;
            u.x = *reinterpret_cast<unsigned*>(&h0);
            u.y = *reinterpret_cast<unsigned*>(&h1);
            *(uint2*)(xt + r * 136 + c4 * 4) = u;
            stg_cs_u2(x16b + (size_t)r * NTOK + n0 + c4 * 4, u);
        }
        __syncthreads();

        if (tile == 0) {
            unsigned sa = smem_u32(stg);
            for (int i = tid; i < 128 * 32; i += 512) {
                int r = i >> 5, c = i & 31;
                cpasync16(sa + r * 512 + c * 16, xb + (size_t)r * NTOK + n0base + 128 + c * 4);
            }
            CP_COMMIT();
        }

        float acc[2][8][4];
#pragma unroll
        for (int a_ = 0; a_ < 2; a_++)
#pragma unroll
            for (int b_ = 0; b_ < 8; b_++)
#pragma unroll
                for (int c_ = 0; c_ < 4; c_++) acc[a_][b_][c_] = 0.f;

        gemm_t<8, 136>(Wt, xt, acc, rbase, cbase, l);

        float q0 = qb[rbase + lr],      q1 = qb[rbase + lr + 8];
        float q2 = qb[rbase + 16 + lr], q3 = qb[rbase + 16 + lr + 8];
#pragma unroll
        for (int ni = 0; ni < 8; ni++) {
            acc[0][ni][0] += q0; acc[0][ni][1] += q0;
            acc[0][ni][2] += q1; acc[0][ni][3] += q1;
            acc[1][ni][0] += q2; acc[1][ni][1] += q2;
            acc[1][ni][2] += q3; acc[1][ni][3] += q3;
        }

        unsigned kf[8][2], vf[8][2];
#pragma unroll
        for (int mi = 0; mi < 2; mi++) {
#pragma unroll
            for (int ni = 0; ni < 8; ni++) {
                float* c = acc[mi][ni];
                __half2 s2 = __floats2half2_rn(c[0] + c[2], c[1] + c[3]);
                __half2 q2h = __floats2half2_rn(fmaf(c[0], c[0], c[2] * c[2]),
                                                fmaf(c[1], c[1], c[3] * c[3]));
                unsigned su = *reinterpret_cast<unsigned*>(&s2);
                unsigned qu = *reinterpret_cast<unsigned*>(&q2h);
#pragma unroll
                for (int m = 4; m <= 16; m <<= 1) {
                    unsigned so = __shfl_xor_sync(0xffffffffu, su, m);
                    unsigned qo = __shfl_xor_sync(0xffffffffu, qu, m);
                    __half2 rs2 = __hadd2(*reinterpret_cast<__half2*>(&su),
                                          *reinterpret_cast<__half2*>(&so));
                    __half2 rq2 = __hadd2(*reinterpret_cast<__half2*>(&qu),
                                          *reinterpret_cast<__half2*>(&qo));
                    su = *reinterpret_cast<unsigned*>(&rs2);
                    qu = *reinterpret_cast<unsigned*>(&rq2);
                }
                float2 s = __half22float2(*reinterpret_cast<__half2*>(&su));
                float2 q = __half22float2(*reinterpret_cast<__half2*>(&qu));
                float ma = s.x * (1.f / 16.f);
                float va = fmaxf((q.x - 16.f * ma * ma) * (1.f / 15.f), 1e-12f);
                float rsa = rsqrt_fast(va);
                float ia = fmaf(-LN_EPS * rsa, rsa, rsa);
                float mb = s.y * (1.f / 16.f);
                float vb = fmaxf((q.y - 16.f * mb * mb) * (1.f / 15.f), 1e-12f);
                float rsb = rsqrt_fast(vb);
                float ib = fmaf(-LN_EPS * rsb, rsb, rsb);
                float n0v = lw[mi][0] * ((c[0] - ma) * ia) + lb[mi][0];
                float n1v = lw[mi][0] * ((c[1] - mb) * ib) + lb[mi][0];
                float n2v = lw[mi][1] * ((c[2] - ma) * ia) + lb[mi][1];
                float n3v = lw[mi][1] * ((c[3] - mb) * ib) + lb[mi][1];
                unsigned lo = pk2h(n0v, n1v);
                unsigned hi = pk2h(n2v, n3v);
                if (mi == 0) { kf[ni][0] = lo; kf[ni][1] = hi; }
                else         { vf[ni][0] = lo; vf[ni][1] = hi; }
            }
        }

#pragma unroll
        for (int tc = 0; tc < 4; tc++) {
            unsigned a[4] = {kf[2 * tc][0], kf[2 * tc][1], kf[2 * tc + 1][0], kf[2 * tc + 1][1]};
            unsigned b0[2] = {vf[2 * tc][0], vf[2 * tc + 1][0]};
            unsigned b1[2] = {vf[2 * tc][1], vf[2 * tc + 1][1]};
            mma16816h(acc2[0], a, b0);
            mma16816h(acc2[1], a, b1);
        }
    }

    float* base = g_kv + (size_t)(b * HEADS + mw) * 256;
#pragma unroll
    for (int eh = 0; eh < 2; eh++) {
        int e0 = eh * 8 + lc * 2;
        atomicAdd(base + lr * 16 + e0,           acc2[eh][0]);
        atomicAdd(base + lr * 16 + e0 + 1,       acc2[eh][1]);
        atomicAdd(base + (lr + 8) * 16 + e0,     acc2[eh][2]);
        atomicAdd(base + (lr + 8) * 16 + e0 + 1, acc2[eh][3]);
    }
}

// ---------------- kernel 2: compose Meff_b = Wq o kv / N (512 threads) ----------------
__global__ void compose_kernel(const float* __restrict__ qkv_w, const float* __restrict__ qkv_b) {
    __shared__ float kvs[256];
    int g = blockIdx.x, b = blockIdx.y;
    int tid = threadIdx.x;
    int ci = tid & 127;
    int eg = tid >> 7;

    if (tid < 256)
        kvs[tid] = g_kv[(b * HEADS + g) * 256 + tid] * (1.f / (float)NTOK);
    __syncthreads();

    if (tid < 16) {
        float s = 0.f;
#pragma unroll
        for (int d = 0; d < 16; d++) s += qkv_b[48 * g + d] * kvs[d * 16 + tid];
        g_meffb[b * 128 + g * 16 + tid] = s;
    }

    float wq[16];
#pragma unroll
    for (int d = 0; d < 16; d++) wq[d] = qkv_w[(48 * g + d) * 128 + ci];

    __half* mdst = g_meff + ((size_t)b * 128 + g * 16) * 128 + ci;
#pragma unroll
    for (int ee = 0; ee < 4; ee++) {
        int e = eg * 4 + ee;
        float s = 0.f;
#pragma unroll
        for (int d = 0; d < 16; d++) s += wq[d] * kvs[d * 16 + e];
        mdst[e * 128] = __float2half_rn(s);
    }
}

// ---------------- kernel 3: fused av + residual + o1 + gelu + o2 + residual ----------------
#define M4_LDB  264
#define M4_XT   0
#define M4_RT   (128 * M4_LDB * 2)
#define M4_WA   (2 * 128 * M4_LDB * 2)
#define M4_WB   (M4_WA + 128 * 136 * 2)
#define M4_BIAS (M4_WB + 128 * 136 * 2)
#define M4_SMEM (M4_BIAS + 3 * 128 * 4)

__global__ void __launch_bounds__(512, 1) main_kernel(const float* __restrict__ o1_b,
                                                      const float* __restrict__ o2_b,
                                                      float* __restrict__ out) {
    extern __shared__ char smem[];
    __half* xt = (__half*)(smem + M4_XT);
    __half* rt = (__half*)(smem + M4_RT);
    __half* wA = (__half*)(smem + M4_WA);
    __half* wB = (__half*)(smem + M4_WB);
    float* bias = (float*)(smem + M4_BIAS);

    int tid = threadIdx.x;
    int b = blockIdx.y;
    int n0 = blockIdx.x * 256;

    {
        unsigned wa = smem_u32(wA), xa = smem_u32(xt);
        const __half* msrc = g_meff + (size_t)b * 128 * 128;
        const __half* xsrc = g_x16 + (size_t)b * CCH * NTOK + n0;
        for (int i = tid; i < 128 * 16; i += 512) {
            int r = i >> 4, c = i & 15;
            cpasync16(wa + r * 272 + c * 16, msrc + r * 128 + c * 8);
        }
        for (int i = tid; i < 128 * 32; i += 512) {
            int r = i >> 5, c = i & 31;
            cpasync16(xa + r * (M4_LDB * 2) + c * 16, xsrc + (size_t)r * NTOK + c * 8);
        }
        CP_COMMIT();
        unsigned wb = smem_u32(wB);
        for (int i = tid; i < 128 * 16; i += 512) {
            int r = i >> 4, c = i & 15;
            cpasync16(wb + r * 272 + c * 16, g_o1h + r * 128 + c * 8);
        }
        CP_COMMIT();
    }
    if (tid < 128) {
        bias[tid] = g_meffb[b * 128 + tid];
        bias[128 + tid] = o1_b[tid];
        bias[256 + tid] = o2_b[tid];
    }
    CP_WAIT(1);
    __syncthreads();

    int w = tid >> 5, l = tid & 31;
    int lr = l >> 2, lc = l & 3;
    int mw = w >> 2, nw = w & 3;
    int rbase = mw * 32, cbase = nw * 64;

    float acc[2][8][4];
#define ZACC() { _Pragma("unroll") for (int a_=0;a_<2;a_++) _Pragma("unroll") for (int b_=0;b_<8;b_++) _Pragma("unroll") for (int c_=0;c_<4;c_++) acc[a_][b_][c_]=0.f; }

    // ---- phase 1: rt = Meff*x + meffb + x ----
    ZACC();
    gemm_t<8, M4_LDB>(wA, xt, acc, rbase, cbase, l);
    {
        float bm0 = bias[rbase + lr],      bm1 = bias[rbase + lr + 8];
        float bm2 = bias[rbase + 16 + lr], bm3 = bias[rbase + 16 + lr + 8];
#pragma unroll
        for (int mi = 0; mi < 2; mi++) {
            int row = rbase + mi * 16 + lr;
            float ba0 = mi ? bm2 : bm0, ba1 = mi ? bm3 : bm1;
#pragma unroll
            for (int ni = 0; ni < 8; ni++) {
                int col = cbase + ni * 8 + lc * 2;
                __half2 xv0 = *(const __half2*)(xt + row * M4_LDB + col);
                __half2 xv1 = *(const __half2*)(xt + (row + 8) * M4_LDB + col);
                float2 f0 = __half22float2(xv0), f1 = __half22float2(xv1);
                float r00 = acc[mi][ni][0] + ba0 + f0.x;
                float r01 = acc[mi][ni][1] + ba0 + f0.y;
                float r10 = acc[mi][ni][2] + ba1 + f1.x;
                float r11 = acc[mi][ni][3] + ba1 + f1.y;
                *(unsigned*)(rt + row * M4_LDB + col)       = pk2h(r00, r01);
                *(unsigned*)(rt + (row + 8) * M4_LDB + col) = pk2h(r10, r11);
            }
        }
    }
    __syncthreads();   // rt ready; wA reads done (safe to overwrite with o2)

    {
        unsigned wa = smem_u32(wA);
        for (int i = tid; i < 128 * 16; i += 512) {
            int r = i >> 4, c = i & 15;
            cpasync16(wa + r * 272 + c * 16, g_o2h + r * 128 + c * 8);
        }
        CP_COMMIT();
    }

    // ---- phase 2: h1 = gelu(o1 * rt + b1) ----
    ZACC();
    gemm_t<8, M4_LDB>(wB, rt, acc, rbase, cbase, l);
    {
        float b10 = bias[128 + rbase + lr],      b11 = bias[128 + rbase + lr + 8];
        float b12 = bias[128 + rbase + 16 + lr], b13 = bias[128 + rbase + 16 + lr + 8];
#pragma unroll
        for (int mi = 0; mi < 2; mi++) {
            float ba0 = mi ? b12 : b10, ba1 = mi ? b13 : b11;
#pragma unroll
            for (int ni = 0; ni < 8; ni++) {
#pragma unroll
                for (int q = 0; q < 4; q++) {
                    float h = acc[mi][ni][q] + ((q < 2) ? ba0 : ba1);
                    acc[mi][ni][q] = 0.5f * h * (1.f + fast_erf(h * 0.70710678118654752f));
                }
            }
        }
    }
    // global barrier: all phase-2 rt reads done AND everyone's o2 cp.asyncs
    // landed (CP_WAIT before the barrier makes them visible to all threads).
    CP_WAIT(0);
    __syncthreads();
#pragma unroll
    for (int mi = 0; mi < 2; mi++) {
        int row = rbase + mi * 16 + lr;
#pragma unroll
        for (int ni = 0; ni < 8; ni++) {
            int col = cbase + ni * 8 + lc * 2;
            *(unsigned*)(rt + row * M4_LDB + col)       = pk2h(acc[mi][ni][0], acc[mi][ni][1]);
            *(unsigned*)(rt + (row + 8) * M4_LDB + col) = pk2h(acc[mi][ni][2], acc[mi][ni][3]);
        }
    }
    // per-token-group barrier: phase-3 only reads rt columns written by the
    // 4 warps sharing this nw (128 threads). Named barrier id 1+nw.
    asm volatile("bar.sync %0, 128;\n" :: "r"(1 + nw) : "memory");

    // ---- phase 3: out = o2 * h1 + b2 + x (streaming stores) ----
    ZACC();
    gemm_t<8, M4_LDB>(wA, rt, acc, rbase, cbase, l);
    {
        float b20 = bias[256 + rbase + lr],      b21 = bias[256 + rbase + lr + 8];
        float b22 = bias[256 + rbase + 16 + lr], b23 = bias[256 + rbase + 16 + lr + 8];
        float* ob = out + (size_t)b * CCH * NTOK + n0;
#pragma unroll
        for (int mi = 0; mi < 2; mi++) {
            int row = rbase + mi * 16 + lr;
            float ba0 = mi ? b22 : b20, ba1 = mi ? b23 : b21;
#pragma unroll
            for (int ni = 0; ni < 8; ni++) {
                int col = cbase + ni * 8 + lc * 2;
                __half2 xv0 = *(const __half2*)(xt + row * M4_LDB + col);
                __half2 xv1 = *(const __half2*)(xt + (row + 8) * M4_LDB + col);
                float2 f0 = __half22float2(xv0), f1 = __half22float2(xv1);
                float2 o0, o1v;
                o0.x = acc[mi][ni][0] + ba0 + f0.x;
                o0.y = acc[mi][ni][1] + ba0 + f0.y;
                o1v.x = acc[mi][ni][2] + ba1 + f1.x;
                o1v.y = acc[mi][ni][3] + ba1 + f1.y;
                __stcs((float2*)(ob + (size_t)row * NTOK + col), o0);
                __stcs((float2*)(ob + (size_t)(row + 8) * NTOK + col), o1v);
            }
        }
    }
}

// ---------------- launch ----------------
extern "C" void kernel_launch(void* const* d_in, const int* in_sizes, int n_in,
                              void* d_out, int out_size) {
    const float* x     = (const float*)d_in[0];
    const float* qkv_w = (const float*)d_in[1];
    const float* qkv_b = (const float*)d_in[2];
    const float* o1_w  = (const float*)d_in[3];
    const float* o1_b  = (const float*)d_in[4];
    const float* o2_w  = (const float*)d_in[5];
    const float* o2_b  = (const float*)d_in[6];
    const float* kln_w = (const float*)d_in[7];
    const float* kln_b = (const float*)d_in[8];
    const float* vln_w = (const float*)d_in[9];
    const float* vln_b = (const float*)d_in[10];
    float* out = (float*)d_out;

    cudaFuncSetAttribute(kv_kernel, cudaFuncAttributeMaxDynamicSharedMemorySize, KVS_SMEM);
    cudaFuncSetAttribute(main_kernel, cudaFuncAttributeMaxDynamicSharedMemorySize, M4_SMEM);

    prep_kernel<<<128, 256>>>(qkv_w, o1_w, o2_w);

    dim3 g2(NTOK / 256, BATCH);
    kv_kernel<<<g2, 512, KVS_SMEM>>>(x, qkv_b, kln_w, kln_b, vln_w, vln_b);

    dim3 gc(HEADS, BATCH);
    compose_kernel<<<gc, 512>>>(qkv_w, qkv_b);

    dim3 g4(NTOK / 256, BATCH);
    main_kernel<<<g4, 512, M4_SMEM>>>(o1_b, o2_b, out);
}

// round 15
// speedup vs baseline: 1.4739x; 1.0724x over previous
#include <cuda_runtime.h>
#include <cuda_fp16.h>

#define BATCH 8
#define CCH   128
#define NTOK  16384
#define HEADS 8
#define LN_EPS 1e-5f

// ---------------- device scratch ----------------
__device__ float  g_kv[BATCH * HEADS * 16 * 16];
__device__ __half g_wkv[256 * 128];
__device__ __half g_o1h[128 * 128];
__device__ __half g_o2h[128 * 128];
__device__ __half g_meff[BATCH * 128 * 128];
__device__ float  g_meffb[BATCH * 128];
__device__ __half g_x16[(size_t)BATCH * CCH * NTOK];

// ---------------- helpers ----------------
__device__ __forceinline__ unsigned pk2h(float a, float b) {
    __half2 h = __floats2half2_rn(a, b);
    return *reinterpret_cast<unsigned*>(&h);
}

__device__ __forceinline__ void mma16816h(float* c, const unsigned* a, const unsigned* b) {
    asm volatile(
        "mma.sync.aligned.m16n8k16.row.col.f32.f16.f16.f32 "
        "{%0,%1,%2,%3}, {%4,%5,%6,%7}, {%8,%9}, {%0,%1,%2,%3};\n"
        : "+f"(c[0]), "+f"(c[1]), "+f"(c[2]), "+f"(c[3])
        : "r"(a[0]), "r"(a[1]), "r"(a[2]), "r"(a[3]), "r"(b[0]), "r"(b[1]));
}

__device__ __forceinline__ unsigned smem_u32(const void* p) {
    return (unsigned)__cvta_generic_to_shared(p);
}

__device__ __forceinline__ void ldsm4(unsigned& r0, unsigned& r1, unsigned& r2, unsigned& r3,
                                      unsigned addr) {
    asm volatile("ldmatrix.sync.aligned.m8n8.x4.shared.b16 {%0,%1,%2,%3}, [%4];\n"
                 : "=r"(r0), "=r"(r1), "=r"(r2), "=r"(r3) : "r"(addr));
}

__device__ __forceinline__ void ldsm4t(unsigned& r0, unsigned& r1, unsigned& r2, unsigned& r3,
                                       unsigned addr) {
    asm volatile("ldmatrix.sync.aligned.m8n8.x4.trans.shared.b16 {%0,%1,%2,%3}, [%4];\n"
                 : "=r"(r0), "=r"(r1), "=r"(r2), "=r"(r3) : "r"(addr));
}

__device__ __forceinline__ void cpasync16(unsigned s, const void* g) {
    asm volatile("cp.async.cg.shared.global [%0], [%1], 16;\n" :: "r"(s), "l"(g));
}
#define CP_COMMIT() asm volatile("cp.async.commit_group;\n")
#define CP_WAIT(n)  asm volatile("cp.async.wait_group %0;\n" :: "n"(n))

__device__ __forceinline__ float rsqrt_fast(float x) {
    float r;
    asm("rsqrt.approx.f32 %0, %1;\n" : "=f"(r) : "f"(x));
    return r;
}

// fast erf: Abramowitz-Stegun 7.1.26
__device__ __forceinline__ float fast_erf(float x) {
    float ax = fabsf(x);
    float t = __fdividef(1.f, fmaf(0.3275911f, ax, 1.f));
    float p = fmaf(1.061405429f, t, -1.453152027f);
    p = fmaf(p, t, 1.421413741f);
    p = fmaf(p, t, -0.284496736f);
    p = fmaf(p, t, 0.254829592f);
    p *= t;
    float r = 1.f - p * __expf(-ax * ax);
    return copysignf(r, x);
}

// Output-layout GEMM: C[c_out rows][token cols] = A[c_out][k=128] * B[k=128][t].
template <int NI8, int LDB>
__device__ __forceinline__ void gemm_t(const __half* __restrict__ A,
                                       const __half* __restrict__ B,
                                       float (&acc)[2][NI8][4], int rbase, int cbase, int lane) {
    unsigned a_addr = smem_u32(A + (rbase + (lane & 15)) * 136 + ((lane >> 4) << 3));
    unsigned b_addr = smem_u32(B + (lane & 15) * LDB + cbase + ((lane >> 4) << 3));
#pragma unroll
    for (int kc = 0; kc < 128; kc += 16) {
        unsigned a[2][4];
        ldsm4(a[0][0], a[0][1], a[0][2], a[0][3], a_addr);
        ldsm4(a[1][0], a[1][1], a[1][2], a[1][3], a_addr + 16 * 136 * 2);
#pragma unroll
        for (int g = 0; g < NI8 / 2; g++) {
            unsigned b0, b1, b2, b3;
            ldsm4t(b0, b1, b2, b3, b_addr + g * 32);
            unsigned bl[2] = {b0, b1}, bh[2] = {b2, b3};
            mma16816h(acc[0][2 * g],     a[0], bl);
            mma16816h(acc[1][2 * g],     a[1], bl);
            mma16816h(acc[0][2 * g + 1], a[0], bh);
            mma16816h(acc[1][2 * g + 1], a[1], bh);
        }
        a_addr += 32;
        b_addr += 16 * LDB * 2;
    }
}

// ---------------- kernel 0: weight prep ----------------
__global__ void prep_kernel(const float* __restrict__ qkv_w,
                            const float* __restrict__ o1_w,
                            const float* __restrict__ o2_w) {
    int idx = blockIdx.x * blockDim.x + threadIdx.x;
    int nthr = gridDim.x * blockDim.x;
    for (int i = idx; i < BATCH * HEADS * 16 * 16; i += nthr) g_kv[i] = 0.f;
    for (int i = idx; i < 256 * 128; i += nthr) {
        int r = i >> 7, c = i & 127;
        int h = r >> 5, j = r & 31;
        int src = (j < 16) ? (48 * h + 16 + j) : (48 * h + 32 + (j - 16));
        g_wkv[i] = __float2half_rn(qkv_w[src * 128 + c]);
    }
    for (int i = idx; i < 128 * 128; i += nthr) {
        g_o1h[i] = __float2half_rn(o1_w[i]);
        g_o2h[i] = __float2half_rn(o2_w[i]);
    }
}

// ---------------- kernel 1: x->fp16 + k,v projection + register-LN + register-kv MMA ----------------
#define KVS_WT    0
#define KVS_XT0   (256 * 136 * 2)
#define KVS_XT1   (KVS_XT0 + 128 * 136 * 2)
#define KVS_STAGE (KVS_XT1 + 128 * 136 * 2)
#define KVS_QB    (KVS_STAGE + 128 * 128 * 4)
#define KVS_SMEM  (KVS_QB + 256 * 4)

__global__ void __launch_bounds__(512, 1) kv_kernel(const float* __restrict__ x,
                                                    const float* __restrict__ qkv_b,
                                                    const float* __restrict__ kln_w,
                                                    const float* __restrict__ kln_b,
                                                    const float* __restrict__ vln_w,
                                                    const float* __restrict__ vln_b) {
    extern __shared__ char smem[];
    __half* Wt = (__half*)(smem + KVS_WT);
    __half* xt0 = (__half*)(smem + KVS_XT0);
    __half* xt1 = (__half*)(smem + KVS_XT1);
    float* stg = (float*)(smem + KVS_STAGE);
    float* qb = (float*)(smem + KVS_QB);

    int tid = threadIdx.x;
    int b = blockIdx.y;
    const float* xb = x + (size_t)b * CCH * NTOK;
    __half* x16b = g_x16 + (size_t)b * CCH * NTOK;
    int n0base = blockIdx.x * 256;

    {
        unsigned wt = smem_u32(Wt);
        for (int i = tid; i < 256 * 16; i += 512) {
            int r = i >> 4, c = i & 15;
            cpasync16(wt + r * 272 + c * 16, g_wkv + r * 128 + c * 8);
        }
        unsigned sa = smem_u32(stg);
        for (int i = tid; i < 128 * 32; i += 512) {
            int r = i >> 5, c = i & 31;
            cpasync16(sa + r * 512 + c * 16, xb + (size_t)r * NTOK + n0base + c * 4);
        }
        CP_COMMIT();
    }
    if (tid < 256) {
        int h = tid >> 5, j = tid & 31;
        int src_r = (j < 16) ? (48 * h + 16 + j) : (48 * h + 32 + (j - 16));
        qb[tid] = qkv_b[src_r];
    }

    int w = tid >> 5, l = tid & 31;
    int lr = l >> 2, lc = l & 3;
    int mw = w >> 1;
    int nw = w & 1;
    int rbase = mw * 32, cbase = nw * 64;

    float lw[2][2], lb[2][2];
    lw[0][0] = kln_w[mw * 16 + lr];     lw[0][1] = kln_w[mw * 16 + lr + 8];
    lb[0][0] = kln_b[mw * 16 + lr];     lb[0][1] = kln_b[mw * 16 + lr + 8];
    lw[1][0] = vln_w[mw * 16 + lr];     lw[1][1] = vln_w[mw * 16 + lr + 8];
    lb[1][0] = vln_b[mw * 16 + lr];     lb[1][1] = vln_b[mw * 16 + lr + 8];

    float acc2[2][4];
#pragma unroll
    for (int e = 0; e < 2; e++)
#pragma unroll
        for (int q = 0; q < 4; q++) acc2[e][q] = 0.f;

#pragma unroll
    for (int tile = 0; tile < 2; tile++) {
        int n0 = n0base + tile * 128;
        __half* xt = tile ? xt1 : xt0;

        CP_WAIT(0);
        __syncthreads();

#pragma unroll
        for (int k = 0; k < 8; k++) {
            int i = tid + k * 512;
            int r = i >> 5, c4 = i & 31;
            float4 v = *(const float4*)(stg + r * 128 + c4 * 4);
            __half2 h0 = __floats2half2_rn(v.x, v.y);
            __half2 h1 = __floats2half2_rn(v.z, v.w);
            uint2 u;
            u.x = *reinterpret_cast<unsigned*>(&h0);
            u.y = *reinterpret_cast<unsigned*>(&h1);
            *(uint2*)(xt + r * 136 + c4 * 4) = u;
            *(uint2*)(x16b + (size_t)r * NTOK + n0 + c4 * 4) = u;
        }
        __syncthreads();

        if (tile == 0) {
            unsigned sa = smem_u32(stg);
            for (int i = tid; i < 128 * 32; i += 512) {
                int r = i >> 5, c = i & 31;
                cpasync16(sa + r * 512 + c * 16, xb + (size_t)r * NTOK + n0base + 128 + c * 4);
            }
            CP_COMMIT();
        }

        float acc[2][8][4];
#pragma unroll
        for (int a_ = 0; a_ < 2; a_++)
#pragma unroll
            for (int b_ = 0; b_ < 8; b_++)
#pragma unroll
                for (int c_ = 0; c_ < 4; c_++) acc[a_][b_][c_] = 0.f;

        gemm_t<8, 136>(Wt, xt, acc, rbase, cbase, l);

        float q0 = qb[rbase + lr],      q1 = qb[rbase + lr + 8];
        float q2 = qb[rbase + 16 + lr], q3 = qb[rbase + 16 + lr + 8];
#pragma unroll
        for (int ni = 0; ni < 8; ni++) {
            acc[0][ni][0] += q0; acc[0][ni][1] += q0;
            acc[0][ni][2] += q1; acc[0][ni][3] += q1;
            acc[1][ni][0] += q2; acc[1][ni][1] += q2;
            acc[1][ni][2] += q3; acc[1][ni][3] += q3;
        }

        unsigned kf[8][2], vf[8][2];
#pragma unroll
        for (int mi = 0; mi < 2; mi++) {
#pragma unroll
            for (int ni = 0; ni < 8; ni++) {
                float* c = acc[mi][ni];
                __half2 s2 = __floats2half2_rn(c[0] + c[2], c[1] + c[3]);
                __half2 q2h = __floats2half2_rn(fmaf(c[0], c[0], c[2] * c[2]),
                                                fmaf(c[1], c[1], c[3] * c[3]));
                unsigned su = *reinterpret_cast<unsigned*>(&s2);
                unsigned qu = *reinterpret_cast<unsigned*>(&q2h);
#pragma unroll
                for (int m = 4; m <= 16; m <<= 1) {
                    unsigned so = __shfl_xor_sync(0xffffffffu, su, m);
                    unsigned qo = __shfl_xor_sync(0xffffffffu, qu, m);
                    __half2 rs2 = __hadd2(*reinterpret_cast<__half2*>(&su),
                                          *reinterpret_cast<__half2*>(&so));
                    __half2 rq2 = __hadd2(*reinterpret_cast<__half2*>(&qu),
                                          *reinterpret_cast<__half2*>(&qo));
                    su = *reinterpret_cast<unsigned*>(&rs2);
                    qu = *reinterpret_cast<unsigned*>(&rq2);
                }
                float2 s = __half22float2(*reinterpret_cast<__half2*>(&su));
                float2 q = __half22float2(*reinterpret_cast<__half2*>(&qu));
                float ma = s.x * (1.f / 16.f);
                float va = fmaxf((q.x - 16.f * ma * ma) * (1.f / 15.f), 1e-12f);
                float rsa = rsqrt_fast(va);
                float ia = fmaf(-LN_EPS * rsa, rsa, rsa);
                float mb = s.y * (1.f / 16.f);
                float vb = fmaxf((q.y - 16.f * mb * mb) * (1.f / 15.f), 1e-12f);
                float rsb = rsqrt_fast(vb);
                float ib = fmaf(-LN_EPS * rsb, rsb, rsb);
                float n0v = lw[mi][0] * ((c[0] - ma) * ia) + lb[mi][0];
                float n1v = lw[mi][0] * ((c[1] - mb) * ib) + lb[mi][0];
                float n2v = lw[mi][1] * ((c[2] - ma) * ia) + lb[mi][1];
                float n3v = lw[mi][1] * ((c[3] - mb) * ib) + lb[mi][1];
                unsigned lo = pk2h(n0v, n1v);
                unsigned hi = pk2h(n2v, n3v);
                if (mi == 0) { kf[ni][0] = lo; kf[ni][1] = hi; }
                else         { vf[ni][0] = lo; vf[ni][1] = hi; }
            }
        }

#pragma unroll
        for (int tc = 0; tc < 4; tc++) {
            unsigned a[4] = {kf[2 * tc][0], kf[2 * tc][1], kf[2 * tc + 1][0], kf[2 * tc + 1][1]};
            unsigned b0[2] = {vf[2 * tc][0], vf[2 * tc + 1][0]};
            unsigned b1[2] = {vf[2 * tc][1], vf[2 * tc + 1][1]};
            mma16816h(acc2[0], a, b0);
            mma16816h(acc2[1], a, b1);
        }
    }

    float* base = g_kv + (size_t)(b * HEADS + mw) * 256;
#pragma unroll
    for (int eh = 0; eh < 2; eh++) {
        int e0 = eh * 8 + lc * 2;
        atomicAdd(base + lr * 16 + e0,           acc2[eh][0]);
        atomicAdd(base + lr * 16 + e0 + 1,       acc2[eh][1]);
        atomicAdd(base + (lr + 8) * 16 + e0,     acc2[eh][2]);
        atomicAdd(base + (lr + 8) * 16 + e0 + 1, acc2[eh][3]);
    }
}

// ---------------- kernel 2: compose Meff_b = Wq o kv / N (512 threads) ----------------
__global__ void compose_kernel(const float* __restrict__ qkv_w, const float* __restrict__ qkv_b) {
    __shared__ float kvs[256];
    int g = blockIdx.x, b = blockIdx.y;
    int tid = threadIdx.x;
    int ci = tid & 127;
    int eg = tid >> 7;

    if (tid < 256)
        kvs[tid] = g_kv[(b * HEADS + g) * 256 + tid] * (1.f / (float)NTOK);
    __syncthreads();

    if (tid < 16) {
        float s = 0.f;
#pragma unroll
        for (int d = 0; d < 16; d++) s += qkv_b[48 * g + d] * kvs[d * 16 + tid];
        g_meffb[b * 128 + g * 16 + tid] = s;
    }

    float wq[16];
#pragma unroll
    for (int d = 0; d < 16; d++) wq[d] = qkv_w[(48 * g + d) * 128 + ci];

    __half* mdst = g_meff + ((size_t)b * 128 + g * 16) * 128 + ci;
#pragma unroll
    for (int ee = 0; ee < 4; ee++) {
        int e = eg * 4 + ee;
        float s = 0.f;
#pragma unroll
        for (int d = 0; d < 16; d++) s += wq[d] * kvs[d * 16 + e];
        mdst[e * 128] = __float2half_rn(s);
    }
}

// ---------------- kernel 3: persistent fused main ----------------
// grid = #SMs, 512 threads. 1024 jobs of 128 tokens, contiguous static ranges.
#define NJOBS  1024
#define MP_LD  136
#define MP_T   (128 * MP_LD * 2)
#define MP_XT0 0
#define MP_XT1 (1 * MP_T)
#define MP_RT  (2 * MP_T)
#define MP_WM  (3 * MP_T)
#define MP_W1  (4 * MP_T)
#define MP_W2  (5 * MP_T)
#define MP_BIAS (6 * MP_T)
#define MP_SMEM (MP_BIAS + 3 * 128 * 4)

__global__ void __launch_bounds__(512, 1) main_kernel(const float* __restrict__ o1_b,
                                                      const float* __restrict__ o2_b,
                                                      float* __restrict__ out) {
    extern __shared__ char smem[];
    __half* xtb[2] = {(__half*)(smem + MP_XT0), (__half*)(smem + MP_XT1)};
    __half* rt = (__half*)(smem + MP_RT);
    __half* wM = (__half*)(smem + MP_WM);
    __half* w1 = (__half*)(smem + MP_W1);
    __half* w2 = (__half*)(smem + MP_W2);
    float* bias = (float*)(smem + MP_BIAS);

    int tid = threadIdx.x;
    int nb = gridDim.x;
    int js = (int)(((long long)blockIdx.x * NJOBS) / nb);
    int je = (int)(((long long)(blockIdx.x + 1) * NJOBS) / nb);
    if (js >= je) return;

    // group 0: o1, o2, and xt for first job
    {
        unsigned a1 = smem_u32(w1), a2 = smem_u32(w2);
        for (int i = tid; i < 128 * 16; i += 512) {
            int r = i >> 4, c = i & 15;
            cpasync16(a1 + r * 272 + c * 16, g_o1h + r * 128 + c * 8);
            cpasync16(a2 + r * 272 + c * 16, g_o2h + r * 128 + c * 8);
        }
        int b0_ = js >> 7, n00 = (js & 127) << 7;
        const __half* xsrc = g_x16 + (size_t)b0_ * CCH * NTOK + n00;
        unsigned xa = smem_u32(xtb[0]);
        for (int i = tid; i < 128 * 16; i += 512) {
            int r = i >> 4, c = i & 15;
            cpasync16(xa + r * 272 + c * 16, xsrc + (size_t)r * NTOK + c * 8);
        }
        CP_COMMIT();
    }
    if (tid < 128) {
        bias[128 + tid] = o1_b[tid];
        bias[256 + tid] = o2_b[tid];
    }

    int w = tid >> 5, l = tid & 31;
    int lr = l >> 2, lc = l & 3;
    int mw = w >> 2, nw = w & 3;      // 4 row groups x 4 col groups (128x128)
    int rbase = mw * 32, cbase = nw * 32;

    int cur_b = -1;
    int buf = 0;

    for (int j = js; j < je; j++) {
        int b = j >> 7;
        int n0 = (j & 127) << 7;

        // prefetch next job's x tile into the other buffer.
        // SAFE: previous iteration ends with __syncthreads(), so no warp is
        // still reading xtb[buf^1] (the buffer read in the previous job).
        if (j + 1 < je) {
            int jn = j + 1;
            const __half* xsrc = g_x16 + (size_t)(jn >> 7) * CCH * NTOK + ((jn & 127) << 7);
            unsigned xa = smem_u32(xtb[buf ^ 1]);
            for (int i = tid; i < 128 * 16; i += 512) {
                int r = i >> 4, c = i & 15;
                cpasync16(xa + r * 272 + c * 16, xsrc + (size_t)r * NTOK + c * 8);
            }
        }
        CP_COMMIT();

        if (b != cur_b) {
            if (tid < 128) bias[tid] = g_meffb[b * 128 + tid];
            unsigned wa = smem_u32(wM);
            const __half* msrc = g_meff + (size_t)b * 128 * 128;
            for (int i = tid; i < 128 * 16; i += 512) {
                int r = i >> 4, c = i & 15;
                cpasync16(wa + r * 272 + c * 16, msrc + r * 128 + c * 8);
            }
            CP_COMMIT();
            CP_WAIT(0);          // drains everything (incl. prefetch) — rare
            cur_b = b;
        } else {
            CP_WAIT(1);          // current xt ready; next prefetch stays in flight
        }
        __syncthreads();

        const __half* xt = xtb[buf];
        float acc[2][4][4];
#define ZACC4() { _Pragma("unroll") for (int a_=0;a_<2;a_++) _Pragma("unroll") for (int b_=0;b_<4;b_++) _Pragma("unroll") for (int c_=0;c_<4;c_++) acc[a_][b_][c_]=0.f; }

        // ---- phase 1: rt = Meff*x + meffb + x ----
        ZACC4();
        gemm_t<4, MP_LD>(wM, xt, acc, rbase, cbase, l);
        {
            float bm0 = bias[rbase + lr],      bm1 = bias[rbase + lr + 8];
            float bm2 = bias[rbase + 16 + lr], bm3 = bias[rbase + 16 + lr + 8];
#pragma unroll
            for (int mi = 0; mi < 2; mi++) {
                int row = rbase + mi * 16 + lr;
                float ba0 = mi ? bm2 : bm0, ba1 = mi ? bm3 : bm1;
#pragma unroll
                for (int ni = 0; ni < 4; ni++) {
                    int col = cbase + ni * 8 + lc * 2;
                    __half2 xv0 = *(const __half2*)(xt + row * MP_LD + col);
                    __half2 xv1 = *(const __half2*)(xt + (row + 8) * MP_LD + col);
                    float2 f0 = __half22float2(xv0), f1 = __half22float2(xv1);
                    *(unsigned*)(rt + row * MP_LD + col) =
                        pk2h(acc[mi][ni][0] + ba0 + f0.x, acc[mi][ni][1] + ba0 + f0.y);
                    *(unsigned*)(rt + (row + 8) * MP_LD + col) =
                        pk2h(acc[mi][ni][2] + ba1 + f1.x, acc[mi][ni][3] + ba1 + f1.y);
                }
            }
        }
        __syncthreads();

        // ---- phase 2: h1 = gelu(o1 * rt + b1) ----
        ZACC4();
        gemm_t<4, MP_LD>(w1, rt, acc, rbase, cbase, l);
        {
            float b10 = bias[128 + rbase + lr],      b11 = bias[128 + rbase + lr + 8];
            float b12 = bias[128 + rbase + 16 + lr], b13 = bias[128 + rbase + 16 + lr + 8];
#pragma unroll
            for (int mi = 0; mi < 2; mi++) {
                float ba0 = mi ? b12 : b10, ba1 = mi ? b13 : b11;
#pragma unroll
                for (int ni = 0; ni < 4; ni++) {
#pragma unroll
                    for (int q = 0; q < 4; q++) {
                        float h = acc[mi][ni][q] + ((q < 2) ? ba0 : ba1);
                        acc[mi][ni][q] = 0.5f * h * (1.f + fast_erf(h * 0.70710678118654752f));
                    }
                }
            }
        }
        __syncthreads();   // all rt reads done
#pragma unroll
        for (int mi = 0; mi < 2; mi++) {
            int row = rbase + mi * 16 + lr;
#pragma unroll
            for (int ni = 0; ni < 4; ni++) {
                int col = cbase + ni * 8 + lc * 2;
                *(unsigned*)(rt + row * MP_LD + col)       = pk2h(acc[mi][ni][0], acc[mi][ni][1]);
                *(unsigned*)(rt + (row + 8) * MP_LD + col) = pk2h(acc[mi][ni][2], acc[mi][ni][3]);
            }
        }
        __syncthreads();

        // ---- phase 3: out = o2 * h1 + b2 + x ----
        ZACC4();
        gemm_t<4, MP_LD>(w2, rt, acc, rbase, cbase, l);
        {
            float b20 = bias[256 + rbase + lr],      b21 = bias[256 + rbase + lr + 8];
            float b22 = bias[256 + rbase + 16 + lr], b23 = bias[256 + rbase + 16 + lr + 8];
            float* ob = out + (size_t)b * CCH * NTOK + n0;
#pragma unroll
            for (int mi = 0; mi < 2; mi++) {
                int row = rbase + mi * 16 + lr;
                float ba0 = mi ? b22 : b20, ba1 = mi ? b23 : b21;
#pragma unroll
                for (int ni = 0; ni < 4; ni++) {
                    int col = cbase + ni * 8 + lc * 2;
                    __half2 xv0 = *(const __half2*)(xt + row * MP_LD + col);
                    __half2 xv1 = *(const __half2*)(xt + (row + 8) * MP_LD + col);
                    float2 f0 = __half22float2(xv0), f1 = __half22float2(xv1);
                    float2 o0, o1v;
                    o0.x = acc[mi][ni][0] + ba0 + f0.x;
                    o0.y = acc[mi][ni][1] + ba0 + f0.y;
                    o1v.x = acc[mi][ni][2] + ba1 + f1.x;
                    o1v.y = acc[mi][ni][3] + ba1 + f1.y;
                    __stcs((float2*)(ob + (size_t)row * NTOK + col), o0);
                    __stcs((float2*)(ob + (size_t)(row + 8) * NTOK + col), o1v);
                }
            }
        }
        // CRITICAL: fence phase-3 xt reads before next iteration's prefetch
        // overwrites xtb[buf] (which becomes the prefetch target after flip).
        __syncthreads();
        buf ^= 1;
    }
}

// ---------------- launch ----------------
extern "C" void kernel_launch(void* const* d_in, const int* in_sizes, int n_in,
                              void* d_out, int out_size) {
    const float* x     = (const float*)d_in[0];
    const float* qkv_w = (const float*)d_in[1];
    const float* qkv_b = (const float*)d_in[2];
    const float* o1_w  = (const float*)d_in[3];
    const float* o1_b  = (const float*)d_in[4];
    const float* o2_w  = (const float*)d_in[5];
    const float* o2_b  = (const float*)d_in[6];
    const float* kln_w = (const float*)d_in[7];
    const float* kln_b = (const float*)d_in[8];
    const float* vln_w = (const float*)d_in[9];
    const float* vln_b = (const float*)d_in[10];
    float* out = (float*)d_out;

    cudaFuncSetAttribute(kv_kernel, cudaFuncAttributeMaxDynamicSharedMemorySize, KVS_SMEM);
    cudaFuncSetAttribute(main_kernel, cudaFuncAttributeMaxDynamicSharedMemorySize, MP_SMEM);

    int dev = 0;
    cudaGetDevice(&dev);
    int nsm = 148;
    cudaDeviceGetAttribute(&nsm, cudaDevAttrMultiProcessorCount, dev);
    if (nsm > NJOBS) nsm = NJOBS;
    if (nsm < 1) nsm = 1;

    prep_kernel<<<128, 256>>>(qkv_w, o1_w, o2_w);

    dim3 g2(NTOK / 256, BATCH);
    kv_kernel<<<g2, 512, KVS_SMEM>>>(x, qkv_b, kln_w, kln_b, vln_w, vln_b);

    dim3 gc(HEADS, BATCH);
    compose_kernel<<<gc, 512>>>(qkv_w, qkv_b);

    main_kernel<<<nsm, 512, MP_SMEM>>>(o1_b, o2_b, out);
}

// round 16
// speedup vs baseline: 1.5772x; 1.0700x over previous
#include <cuda_runtime.h>
#include <cuda_fp16.h>

#define BATCH 8
#define CCH   128
#define NTOK  16384
#define HEADS 8
#define LN_EPS 1e-5f

// ---------------- device scratch ----------------
__device__ float  g_kv[BATCH * HEADS * 16 * 16];
__device__ __half g_wkv[256 * 128];
__device__ __half g_o1h[128 * 128];
__device__ __half g_o2h[128 * 128];
__device__ __half g_meff[BATCH * 128 * 128];
__device__ float  g_meffb[BATCH * 128];
__device__ __half g_x16[(size_t)BATCH * CCH * NTOK];

// ---------------- helpers ----------------
__device__ __forceinline__ unsigned pk2h(float a, float b) {
    __half2 h = __floats2half2_rn(a, b);
    return *reinterpret_cast<unsigned*>(&h);
}

__device__ __forceinline__ void mma16816h(float* c, const unsigned* a, const unsigned* b) {
    asm volatile(
        "mma.sync.aligned.m16n8k16.row.col.f32.f16.f16.f32 "
        "{%0,%1,%2,%3}, {%4,%5,%6,%7}, {%8,%9}, {%0,%1,%2,%3};\n"
        : "+f"(c[0]), "+f"(c[1]), "+f"(c[2]), "+f"(c[3])
        : "r"(a[0]), "r"(a[1]), "r"(a[2]), "r"(a[3]), "r"(b[0]), "r"(b[1]));
}

__device__ __forceinline__ unsigned smem_u32(const void* p) {
    return (unsigned)__cvta_generic_to_shared(p);
}

__device__ __forceinline__ void ldsm4(unsigned& r0, unsigned& r1, unsigned& r2, unsigned& r3,
                                      unsigned addr) {
    asm volatile("ldmatrix.sync.aligned.m8n8.x4.shared.b16 {%0,%1,%2,%3}, [%4];\n"
                 : "=r"(r0), "=r"(r1), "=r"(r2), "=r"(r3) : "r"(addr));
}

__device__ __forceinline__ void ldsm4t(unsigned& r0, unsigned& r1, unsigned& r2, unsigned& r3,
                                       unsigned addr) {
    asm volatile("ldmatrix.sync.aligned.m8n8.x4.trans.shared.b16 {%0,%1,%2,%3}, [%4];\n"
                 : "=r"(r0), "=r"(r1), "=r"(r2), "=r"(r3) : "r"(addr));
}

__device__ __forceinline__ void cpasync16(unsigned s, const void* g) {
    asm volatile("cp.async.cg.shared.global [%0], [%1], 16;\n" :: "r"(s), "l"(g));
}
#define CP_COMMIT() asm volatile("cp.async.commit_group;\n")
#define CP_WAIT(n)  asm volatile("cp.async.wait_group %0;\n" :: "n"(n))

__device__ __forceinline__ float rsqrt_fast(float x) {
    float r;
    asm("rsqrt.approx.f32 %0, %1;\n" : "=f"(r) : "f"(x));
    return r;
}

// fast erf: Abramowitz-Stegun 7.1.26
__device__ __forceinline__ float fast_erf(float x) {
    float ax = fabsf(x);
    float t = __fdividef(1.f, fmaf(0.3275911f, ax, 1.f));
    float p = fmaf(1.061405429f, t, -1.453152027f);
    p = fmaf(p, t, 1.421413741f);
    p = fmaf(p, t, -0.284496736f);
    p = fmaf(p, t, 0.254829592f);
    p *= t;
    float r = 1.f - p * __expf(-ax * ax);
    return copysignf(r, x);
}

// Output-layout GEMM: C[c_out rows][token cols] = A[c_out][k=128] * B[k=128][t].
template <int NI8, int LDB>
__device__ __forceinline__ void gemm_t(const __half* __restrict__ A,
                                       const __half* __restrict__ B,
                                       float (&acc)[2][NI8][4], int rbase, int cbase, int lane) {
    unsigned a_addr = smem_u32(A + (rbase + (lane & 15)) * 136 + ((lane >> 4) << 3));
    unsigned b_addr = smem_u32(B + (lane & 15) * LDB + cbase + ((lane >> 4) << 3));
#pragma unroll
    for (int kc = 0; kc < 128; kc += 16) {
        unsigned a[2][4];
        ldsm4(a[0][0], a[0][1], a[0][2], a[0][3], a_addr);
        ldsm4(a[1][0], a[1][1], a[1][2], a[1][3], a_addr + 16 * 136 * 2);
#pragma unroll
        for (int g = 0; g < NI8 / 2; g++) {
            unsigned b0, b1, b2, b3;
            ldsm4t(b0, b1, b2, b3, b_addr + g * 32);
            unsigned bl[2] = {b0, b1}, bh[2] = {b2, b3};
            mma16816h(acc[0][2 * g],     a[0], bl);
            mma16816h(acc[1][2 * g],     a[1], bl);
            mma16816h(acc[0][2 * g + 1], a[0], bh);
            mma16816h(acc[1][2 * g + 1], a[1], bh);
        }
        a_addr += 32;
        b_addr += 16 * LDB * 2;
    }
}

// ---------------- kernel 0: weight prep ----------------
__global__ void prep_kernel(const float* __restrict__ qkv_w,
                            const float* __restrict__ o1_w,
                            const float* __restrict__ o2_w) {
    int idx = blockIdx.x * blockDim.x + threadIdx.x;
    int nthr = gridDim.x * blockDim.x;
    for (int i = idx; i < BATCH * HEADS * 16 * 16; i += nthr) g_kv[i] = 0.f;
    for (int i = idx; i < 256 * 128; i += nthr) {
        int r = i >> 7, c = i & 127;
        int h = r >> 5, j = r & 31;
        int src = (j < 16) ? (48 * h + 16 + j) : (48 * h + 32 + (j - 16));
        g_wkv[i] = __float2half_rn(qkv_w[src * 128 + c]);
    }
    for (int i = idx; i < 128 * 128; i += nthr) {
        g_o1h[i] = __float2half_rn(o1_w[i]);
        g_o2h[i] = __float2half_rn(o2_w[i]);
    }
}

// ---------------- kernel 1: persistent x->fp16 + k,v projection + reg-LN + reg-kv MMA ----------------
// grid = #SMs, 512 threads. 1024 jobs of 128 tokens.
#define KVJOBS    1024
#define KVS_WT    0
#define KVS_XT    (256 * 136 * 2)
#define KVS_STAGE (KVS_XT + 128 * 136 * 2)
#define KVS_QB    (KVS_STAGE + 128 * 128 * 4)
#define KVS_SMEM  (KVS_QB + 256 * 4)

__global__ void __launch_bounds__(512, 1) kv_kernel(const float* __restrict__ x,
                                                    const float* __restrict__ qkv_b,
                                                    const float* __restrict__ kln_w,
                                                    const float* __restrict__ kln_b,
                                                    const float* __restrict__ vln_w,
                                                    const float* __restrict__ vln_b) {
    extern __shared__ char smem[];
    __half* Wt = (__half*)(smem + KVS_WT);
    __half* xt = (__half*)(smem + KVS_XT);
    float* stg = (float*)(smem + KVS_STAGE);
    float* qb = (float*)(smem + KVS_QB);

    int tid = threadIdx.x;
    int nb = gridDim.x;
    int js = (int)(((long long)blockIdx.x * KVJOBS) / nb);
    int je = (int)(((long long)(blockIdx.x + 1) * KVJOBS) / nb);
    if (js >= je) return;

    // init group: weights + first job's stage
    {
        unsigned wt = smem_u32(Wt);
        for (int i = tid; i < 256 * 16; i += 512) {
            int r = i >> 4, c = i & 15;
            cpasync16(wt + r * 272 + c * 16, g_wkv + r * 128 + c * 8);
        }
        int b0_ = js >> 7, n00 = (js & 127) << 7;
        const float* xsrc = x + (size_t)b0_ * CCH * NTOK + n00;
        unsigned sa = smem_u32(stg);
        for (int i = tid; i < 128 * 32; i += 512) {
            int r = i >> 5, c = i & 31;
            cpasync16(sa + r * 512 + c * 16, xsrc + (size_t)r * NTOK + c * 4);
        }
        CP_COMMIT();
    }
    if (tid < 256) {
        int h = tid >> 5, j = tid & 31;
        int src_r = (j < 16) ? (48 * h + 16 + j) : (48 * h + 32 + (j - 16));
        qb[tid] = qkv_b[src_r];
    }

    int w = tid >> 5, l = tid & 31;
    int lr = l >> 2, lc = l & 3;
    int mw = w >> 1;      // head
    int nw = w & 1;       // token half
    int rbase = mw * 32, cbase = nw * 64;

    float lw[2][2], lb[2][2];
    lw[0][0] = kln_w[mw * 16 + lr];     lw[0][1] = kln_w[mw * 16 + lr + 8];
    lb[0][0] = kln_b[mw * 16 + lr];     lb[0][1] = kln_b[mw * 16 + lr + 8];
    lw[1][0] = vln_w[mw * 16 + lr];     lw[1][1] = vln_w[mw * 16 + lr + 8];
    lb[1][0] = vln_b[mw * 16 + lr];     lb[1][1] = vln_b[mw * 16 + lr + 8];

    float acc2[2][4];
#pragma unroll
    for (int e = 0; e < 2; e++)
#pragma unroll
        for (int q = 0; q < 4; q++) acc2[e][q] = 0.f;

    float q0 = qb[rbase + lr],      q1 = qb[rbase + lr + 8];
    float q2 = qb[rbase + 16 + lr], q3 = qb[rbase + 16 + lr + 8];

    for (int j = js; j < je; j++) {
        int b = j >> 7;
        int n0 = (j & 127) << 7;

        CP_WAIT(0);
        __syncthreads();   // stage ready; previous job's xt reads complete

        // convert stage -> xt (fp16) + g_x16
        __half* x16b = g_x16 + (size_t)b * CCH * NTOK;
#pragma unroll
        for (int k = 0; k < 8; k++) {
            int i = tid + k * 512;
            int r = i >> 5, c4 = i & 31;
            float4 v = *(const float4*)(stg + r * 128 + c4 * 4);
            __half2 h0 = __floats2half2_rn(v.x, v.y);
            __half2 h1 = __floats2half2_rn(v.z, v.w);
            uint2 u;
            u.x = *reinterpret_cast<unsigned*>(&h0);
            u.y = *reinterpret_cast<unsigned*>(&h1);
            *(uint2*)(xt + r * 136 + c4 * 4) = u;
            *(uint2*)(x16b + (size_t)r * NTOK + n0 + c4 * 4) = u;
        }
        __syncthreads();   // xt complete; stage fully consumed

        // prefetch next job's stage (overlaps this job's GEMM)
        if (j + 1 < je) {
            int jn = j + 1;
            const float* xsrc = x + (size_t)(jn >> 7) * CCH * NTOK + ((jn & 127) << 7);
            unsigned sa = smem_u32(stg);
            for (int i = tid; i < 128 * 32; i += 512) {
                int r = i >> 5, c = i & 31;
                cpasync16(sa + r * 512 + c * 16, xsrc + (size_t)r * NTOK + c * 4);
            }
            CP_COMMIT();
        }

        float acc[2][8][4];
#pragma unroll
        for (int a_ = 0; a_ < 2; a_++)
#pragma unroll
            for (int b_ = 0; b_ < 8; b_++)
#pragma unroll
                for (int c_ = 0; c_ < 4; c_++) acc[a_][b_][c_] = 0.f;

        gemm_t<8, 136>(Wt, xt, acc, rbase, cbase, l);

#pragma unroll
        for (int ni = 0; ni < 8; ni++) {
            acc[0][ni][0] += q0; acc[0][ni][1] += q0;
            acc[0][ni][2] += q1; acc[0][ni][3] += q1;
            acc[1][ni][0] += q2; acc[1][ni][1] += q2;
            acc[1][ni][2] += q3; acc[1][ni][3] += q3;
        }

        // register LayerNorm over d=16 (ddof=1, eps on std), half2-packed butterflies
        unsigned kf[8][2], vf[8][2];
#pragma unroll
        for (int mi = 0; mi < 2; mi++) {
#pragma unroll
            for (int ni = 0; ni < 8; ni++) {
                float* c = acc[mi][ni];
                __half2 s2 = __floats2half2_rn(c[0] + c[2], c[1] + c[3]);
                __half2 q2h = __floats2half2_rn(fmaf(c[0], c[0], c[2] * c[2]),
                                                fmaf(c[1], c[1], c[3] * c[3]));
                unsigned su = *reinterpret_cast<unsigned*>(&s2);
                unsigned qu = *reinterpret_cast<unsigned*>(&q2h);
#pragma unroll
                for (int m = 4; m <= 16; m <<= 1) {
                    unsigned so = __shfl_xor_sync(0xffffffffu, su, m);
                    unsigned qo = __shfl_xor_sync(0xffffffffu, qu, m);
                    __half2 rs2 = __hadd2(*reinterpret_cast<__half2*>(&su),
                                          *reinterpret_cast<__half2*>(&so));
                    __half2 rq2 = __hadd2(*reinterpret_cast<__half2*>(&qu),
                                          *reinterpret_cast<__half2*>(&qo));
                    su = *reinterpret_cast<unsigned*>(&rs2);
                    qu = *reinterpret_cast<unsigned*>(&rq2);
                }
                float2 s = __half22float2(*reinterpret_cast<__half2*>(&su));
                float2 q = __half22float2(*reinterpret_cast<__half2*>(&qu));
                float ma = s.x * (1.f / 16.f);
                float va = fmaxf((q.x - 16.f * ma * ma) * (1.f / 15.f), 1e-12f);
                float rsa = rsqrt_fast(va);
                float ia = fmaf(-LN_EPS * rsa, rsa, rsa);
                float mb = s.y * (1.f / 16.f);
                float vb = fmaxf((q.y - 16.f * mb * mb) * (1.f / 15.f), 1e-12f);
                float rsb = rsqrt_fast(vb);
                float ib = fmaf(-LN_EPS * rsb, rsb, rsb);
                float n0v = lw[mi][0] * ((c[0] - ma) * ia) + lb[mi][0];
                float n1v = lw[mi][0] * ((c[1] - mb) * ib) + lb[mi][0];
                float n2v = lw[mi][1] * ((c[2] - ma) * ia) + lb[mi][1];
                float n3v = lw[mi][1] * ((c[3] - mb) * ib) + lb[mi][1];
                unsigned lo = pk2h(n0v, n1v);
                unsigned hi = pk2h(n2v, n3v);
                if (mi == 0) { kf[ni][0] = lo; kf[ni][1] = hi; }
                else         { vf[ni][0] = lo; vf[ni][1] = hi; }
            }
        }

        // kv outer product entirely in registers
#pragma unroll
        for (int tc = 0; tc < 4; tc++) {
            unsigned a[4] = {kf[2 * tc][0], kf[2 * tc][1], kf[2 * tc + 1][0], kf[2 * tc + 1][1]};
            unsigned b0[2] = {vf[2 * tc][0], vf[2 * tc + 1][0]};
            unsigned b1[2] = {vf[2 * tc][1], vf[2 * tc + 1][1]};
            mma16816h(acc2[0], a, b0);
            mma16816h(acc2[1], a, b1);
        }

        // flush accumulators on batch boundary or at end (register-only, no sync needed)
        if (j + 1 >= je || ((j + 1) >> 7) != b) {
            float* base = g_kv + (size_t)(b * HEADS + mw) * 256;
#pragma unroll
            for (int eh = 0; eh < 2; eh++) {
                int e0 = eh * 8 + lc * 2;
                atomicAdd(base + lr * 16 + e0,           acc2[eh][0]);
                atomicAdd(base + lr * 16 + e0 + 1,       acc2[eh][1]);
                atomicAdd(base + (lr + 8) * 16 + e0,     acc2[eh][2]);
                atomicAdd(base + (lr + 8) * 16 + e0 + 1, acc2[eh][3]);
            }
#pragma unroll
            for (int e = 0; e < 2; e++)
#pragma unroll
                for (int q = 0; q < 4; q++) acc2[e][q] = 0.f;
        }
    }
}

// ---------------- kernel 2: compose Meff_b = Wq o kv / N (512 threads) ----------------
__global__ void compose_kernel(const float* __restrict__ qkv_w, const float* __restrict__ qkv_b) {
    __shared__ float kvs[256];
    int g = blockIdx.x, b = blockIdx.y;
    int tid = threadIdx.x;
    int ci = tid & 127;
    int eg = tid >> 7;

    if (tid < 256)
        kvs[tid] = g_kv[(b * HEADS + g) * 256 + tid] * (1.f / (float)NTOK);
    __syncthreads();

    if (tid < 16) {
        float s = 0.f;
#pragma unroll
        for (int d = 0; d < 16; d++) s += qkv_b[48 * g + d] * kvs[d * 16 + tid];
        g_meffb[b * 128 + g * 16 + tid] = s;
    }

    float wq[16];
#pragma unroll
    for (int d = 0; d < 16; d++) wq[d] = qkv_w[(48 * g + d) * 128 + ci];

    __half* mdst = g_meff + ((size_t)b * 128 + g * 16) * 128 + ci;
#pragma unroll
    for (int ee = 0; ee < 4; ee++) {
        int e = eg * 4 + ee;
        float s = 0.f;
#pragma unroll
        for (int d = 0; d < 16; d++) s += wq[d] * kvs[d * 16 + e];
        mdst[e * 128] = __float2half_rn(s);
    }
}

// ---------------- kernel 3: persistent fused main (R15 champion, unchanged) ----------------
#define NJOBS  1024
#define MP_LD  136
#define MP_T   (128 * MP_LD * 2)
#define MP_XT0 0
#define MP_XT1 (1 * MP_T)
#define MP_RT  (2 * MP_T)
#define MP_WM  (3 * MP_T)
#define MP_W1  (4 * MP_T)
#define MP_W2  (5 * MP_T)
#define MP_BIAS (6 * MP_T)
#define MP_SMEM (MP_BIAS + 3 * 128 * 4)

__global__ void __launch_bounds__(512, 1) main_kernel(const float* __restrict__ o1_b,
                                                      const float* __restrict__ o2_b,
                                                      float* __restrict__ out) {
    extern __shared__ char smem[];
    __half* xtb[2] = {(__half*)(smem + MP_XT0), (__half*)(smem + MP_XT1)};
    __half* rt = (__half*)(smem + MP_RT);
    __half* wM = (__half*)(smem + MP_WM);
    __half* w1 = (__half*)(smem + MP_W1);
    __half* w2 = (__half*)(smem + MP_W2);
    float* bias = (float*)(smem + MP_BIAS);

    int tid = threadIdx.x;
    int nb = gridDim.x;
    int js = (int)(((long long)blockIdx.x * NJOBS) / nb);
    int je = (int)(((long long)(blockIdx.x + 1) * NJOBS) / nb);
    if (js >= je) return;

    {
        unsigned a1 = smem_u32(w1), a2 = smem_u32(w2);
        for (int i = tid; i < 128 * 16; i += 512) {
            int r = i >> 4, c = i & 15;
            cpasync16(a1 + r * 272 + c * 16, g_o1h + r * 128 + c * 8);
            cpasync16(a2 + r * 272 + c * 16, g_o2h + r * 128 + c * 8);
        }
        int b0_ = js >> 7, n00 = (js & 127) << 7;
        const __half* xsrc = g_x16 + (size_t)b0_ * CCH * NTOK + n00;
        unsigned xa = smem_u32(xtb[0]);
        for (int i = tid; i < 128 * 16; i += 512) {
            int r = i >> 4, c = i & 15;
            cpasync16(xa + r * 272 + c * 16, xsrc + (size_t)r * NTOK + c * 8);
        }
        CP_COMMIT();
    }
    if (tid < 128) {
        bias[128 + tid] = o1_b[tid];
        bias[256 + tid] = o2_b[tid];
    }

    int w = tid >> 5, l = tid & 31;
    int lr = l >> 2, lc = l & 3;
    int mw = w >> 2, nw = w & 3;
    int rbase = mw * 32, cbase = nw * 32;

    int cur_b = -1;
    int buf = 0;

    for (int j = js; j < je; j++) {
        int b = j >> 7;
        int n0 = (j & 127) << 7;

        if (j + 1 < je) {
            int jn = j + 1;
            const __half* xsrc = g_x16 + (size_t)(jn >> 7) * CCH * NTOK + ((jn & 127) << 7);
            unsigned xa = smem_u32(xtb[buf ^ 1]);
            for (int i = tid; i < 128 * 16; i += 512) {
                int r = i >> 4, c = i & 15;
                cpasync16(xa + r * 272 + c * 16, xsrc + (size_t)r * NTOK + c * 8);
            }
        }
        CP_COMMIT();

        if (b != cur_b) {
            if (tid < 128) bias[tid] = g_meffb[b * 128 + tid];
            unsigned wa = smem_u32(wM);
            const __half* msrc = g_meff + (size_t)b * 128 * 128;
            for (int i = tid; i < 128 * 16; i += 512) {
                int r = i >> 4, c = i & 15;
                cpasync16(wa + r * 272 + c * 16, msrc + r * 128 + c * 8);
            }
            CP_COMMIT();
            CP_WAIT(0);
            cur_b = b;
        } else {
            CP_WAIT(1);
        }
        __syncthreads();

        const __half* xt = xtb[buf];
        float acc[2][4][4];
#define ZACC4() { _Pragma("unroll") for (int a_=0;a_<2;a_++) _Pragma("unroll") for (int b_=0;b_<4;b_++) _Pragma("unroll") for (int c_=0;c_<4;c_++) acc[a_][b_][c_]=0.f; }

        // ---- phase 1: rt = Meff*x + meffb + x ----
        ZACC4();
        gemm_t<4, MP_LD>(wM, xt, acc, rbase, cbase, l);
        {
            float bm0 = bias[rbase + lr],      bm1 = bias[rbase + lr + 8];
            float bm2 = bias[rbase + 16 + lr], bm3 = bias[rbase + 16 + lr + 8];
#pragma unroll
            for (int mi = 0; mi < 2; mi++) {
                int row = rbase + mi * 16 + lr;
                float ba0 = mi ? bm2 : bm0, ba1 = mi ? bm3 : bm1;
#pragma unroll
                for (int ni = 0; ni < 4; ni++) {
                    int col = cbase + ni * 8 + lc * 2;
                    __half2 xv0 = *(const __half2*)(xt + row * MP_LD + col);
                    __half2 xv1 = *(const __half2*)(xt + (row + 8) * MP_LD + col);
                    float2 f0 = __half22float2(xv0), f1 = __half22float2(xv1);
                    *(unsigned*)(rt + row * MP_LD + col) =
                        pk2h(acc[mi][ni][0] + ba0 + f0.x, acc[mi][ni][1] + ba0 + f0.y);
                    *(unsigned*)(rt + (row + 8) * MP_LD + col) =
                        pk2h(acc[mi][ni][2] + ba1 + f1.x, acc[mi][ni][3] + ba1 + f1.y);
                }
            }
        }
        __syncthreads();

        // ---- phase 2: h1 = gelu(o1 * rt + b1) ----
        ZACC4();
        gemm_t<4, MP_LD>(w1, rt, acc, rbase, cbase, l);
        {
            float b10 = bias[128 + rbase + lr],      float_b11 = bias[128 + rbase + lr + 8];
            float b12 = bias[128 + rbase + 16 + lr], b13 = bias[128 + rbase + 16 + lr + 8];
            float b11 = float_b11;
#pragma unroll
            for (int mi = 0; mi < 2; mi++) {
                float ba0 = mi ? b12 : b10, ba1 = mi ? b13 : b11;
#pragma unroll
                for (int ni = 0; ni < 4; ni++) {
#pragma unroll
                    for (int q = 0; q < 4; q++) {
                        float h = acc[mi][ni][q] + ((q < 2) ? ba0 : ba1);
                        acc[mi][ni][q] = 0.5f * h * (1.f + fast_erf(h * 0.70710678118654752f));
                    }
                }
            }
        }
        __syncthreads();
#pragma unroll
        for (int mi = 0; mi < 2; mi++) {
            int row = rbase + mi * 16 + lr;
#pragma unroll
            for (int ni = 0; ni < 4; ni++) {
                int col = cbase + ni * 8 + lc * 2;
                *(unsigned*)(rt + row * MP_LD + col)       = pk2h(acc[mi][ni][0], acc[mi][ni][1]);
                *(unsigned*)(rt + (row + 8) * MP_LD + col) = pk2h(acc[mi][ni][2], acc[mi][ni][3]);
            }
        }
        __syncthreads();

        // ---- phase 3: out = o2 * h1 + b2 + x ----
        ZACC4();
        gemm_t<4, MP_LD>(w2, rt, acc, rbase, cbase, l);
        {
            float b20 = bias[256 + rbase + lr],      b21 = bias[256 + rbase + lr + 8];
            float b22 = bias[256 + rbase + 16 + lr], b23 = bias[256 + rbase + 16 + lr + 8];
            float* ob = out + (size_t)b * CCH * NTOK + n0;
#pragma unroll
            for (int mi = 0; mi < 2; mi++) {
                int row = rbase + mi * 16 + lr;
                float ba0 = mi ? b22 : b20, ba1 = mi ? b23 : b21;
#pragma unroll
                for (int ni = 0; ni < 4; ni++) {
                    int col = cbase + ni * 8 + lc * 2;
                    __half2 xv0 = *(const __half2*)(xt + row * MP_LD + col);
                    __half2 xv1 = *(const __half2*)(xt + (row + 8) * MP_LD + col);
                    float2 f0 = __half22float2(xv0), f1 = __half22float2(xv1);
                    float2 o0, o1v;
                    o0.x = acc[mi][ni][0] + ba0 + f0.x;
                    o0.y = acc[mi][ni][1] + ba0 + f0.y;
                    o1v.x = acc[mi][ni][2] + ba1 + f1.x;
                    o1v.y = acc[mi][ni][3] + ba1 + f1.y;
                    __stcs((float2*)(ob + (size_t)row * NTOK + col), o0);
                    __stcs((float2*)(ob + (size_t)(row + 8) * NTOK + col), o1v);
                }
            }
        }
        __syncthreads();   // fence xt reads before next prefetch overwrites
        buf ^= 1;
    }
}

// ---------------- launch ----------------
extern "C" void kernel_launch(void* const* d_in, const int* in_sizes, int n_in,
                              void* d_out, int out_size) {
    const float* x     = (const float*)d_in[0];
    const float* qkv_w = (const float*)d_in[1];
    const float* qkv_b = (const float*)d_in[2];
    const float* o1_w  = (const float*)d_in[3];
    const float* o1_b  = (const float*)d_in[4];
    const float* o2_w  = (const float*)d_in[5];
    const float* o2_b  = (const float*)d_in[6];
    const float* kln_w = (const float*)d_in[7];
    const float* kln_b = (const float*)d_in[8];
    const float* vln_w = (const float*)d_in[9];
    const float* vln_b = (const float*)d_in[10];
    float* out = (float*)d_out;

    cudaFuncSetAttribute(kv_kernel, cudaFuncAttributeMaxDynamicSharedMemorySize, KVS_SMEM);
    cudaFuncSetAttribute(main_kernel, cudaFuncAttributeMaxDynamicSharedMemorySize, MP_SMEM);

    int dev = 0;
    cudaGetDevice(&dev);
    int nsm = 148;
    cudaDeviceGetAttribute(&nsm, cudaDevAttrMultiProcessorCount, dev);
    if (nsm < 1) nsm = 1;
    int nkv = nsm > KVJOBS ? KVJOBS : nsm;
    int nmn = nsm > NJOBS ? NJOBS : nsm;

    prep_kernel<<<128, 256>>>(qkv_w, o1_w, o2_w);

    kv_kernel<<<nkv, 512, KVS_SMEM>>>(x, qkv_b, kln_w, kln_b, vln_w, vln_b);

    dim3 gc(HEADS, BATCH);
    compose_kernel<<<gc, 512>>>(qkv_w, qkv_b);

    main_kernel<<<nmn, 512, MP_SMEM>>>(o1_b, o2_b, out);
}

// round 17
// speedup vs baseline: 1.6165x; 1.0249x over previous
#include <cuda_runtime.h>
#include <cuda_fp16.h>

#define BATCH 8
#define CCH   128
#define NTOK  16384
#define HEADS 8
#define LN_EPS 1e-5f

// ---------------- device scratch ----------------
__device__ float  g_kv[BATCH * HEADS * 16 * 16];
__device__ __half g_wkv[256 * 128];
__device__ __half g_o1h[128 * 128];
__device__ __half g_o2h[128 * 128];
__device__ __half g_meff[BATCH * 128 * 128];   // holds (Meff + I), fp16
__device__ float  g_meffb[BATCH * 128];
__device__ __half g_x16[(size_t)BATCH * CCH * NTOK];

// ---------------- helpers ----------------
__device__ __forceinline__ unsigned pk2h(float a, float b) {
    __half2 h = __floats2half2_rn(a, b);
    return *reinterpret_cast<unsigned*>(&h);
}

__device__ __forceinline__ void mma16816h(float* c, const unsigned* a, const unsigned* b) {
    asm volatile(
        "mma.sync.aligned.m16n8k16.row.col.f32.f16.f16.f32 "
        "{%0,%1,%2,%3}, {%4,%5,%6,%7}, {%8,%9}, {%0,%1,%2,%3};\n"
        : "+f"(c[0]), "+f"(c[1]), "+f"(c[2]), "+f"(c[3])
        : "r"(a[0]), "r"(a[1]), "r"(a[2]), "r"(a[3]), "r"(b[0]), "r"(b[1]));
}

__device__ __forceinline__ unsigned smem_u32(const void* p) {
    return (unsigned)__cvta_generic_to_shared(p);
}

__device__ __forceinline__ void ldsm4(unsigned& r0, unsigned& r1, unsigned& r2, unsigned& r3,
                                      unsigned addr) {
    asm volatile("ldmatrix.sync.aligned.m8n8.x4.shared.b16 {%0,%1,%2,%3}, [%4];\n"
                 : "=r"(r0), "=r"(r1), "=r"(r2), "=r"(r3) : "r"(addr));
}

__device__ __forceinline__ void ldsm4t(unsigned& r0, unsigned& r1, unsigned& r2, unsigned& r3,
                                       unsigned addr) {
    asm volatile("ldmatrix.sync.aligned.m8n8.x4.trans.shared.b16 {%0,%1,%2,%3}, [%4];\n"
                 : "=r"(r0), "=r"(r1), "=r"(r2), "=r"(r3) : "r"(addr));
}

__device__ __forceinline__ void cpasync16(unsigned s, const void* g) {
    asm volatile("cp.async.cg.shared.global [%0], [%1], 16;\n" :: "r"(s), "l"(g));
}
#define CP_COMMIT() asm volatile("cp.async.commit_group;\n")
#define CP_WAIT(n)  asm volatile("cp.async.wait_group %0;\n" :: "n"(n))

__device__ __forceinline__ float rsqrt_fast(float x) {
    float r;
    asm("rsqrt.approx.f32 %0, %1;\n" : "=f"(r) : "f"(x));
    return r;
}

// fast erf: Abramowitz-Stegun 7.1.26
__device__ __forceinline__ float fast_erf(float x) {
    float ax = fabsf(x);
    float t = __fdividef(1.f, fmaf(0.3275911f, ax, 1.f));
    float p = fmaf(1.061405429f, t, -1.453152027f);
    p = fmaf(p, t, 1.421413741f);
    p = fmaf(p, t, -0.284496736f);
    p = fmaf(p, t, 0.254829592f);
    p *= t;
    float r = 1.f - p * __expf(-ax * ax);
    return copysignf(r, x);
}

// Output-layout GEMM: C[c_out rows][token cols] = A[c_out][k=128] * B[k=128][t].
template <int NI8, int LDB>
__device__ __forceinline__ void gemm_t(const __half* __restrict__ A,
                                       const __half* __restrict__ B,
                                       float (&acc)[2][NI8][4], int rbase, int cbase, int lane) {
    unsigned a_addr = smem_u32(A + (rbase + (lane & 15)) * 136 + ((lane >> 4) << 3));
    unsigned b_addr = smem_u32(B + (lane & 15) * LDB + cbase + ((lane >> 4) << 3));
#pragma unroll
    for (int kc = 0; kc < 128; kc += 16) {
        unsigned a[2][4];
        ldsm4(a[0][0], a[0][1], a[0][2], a[0][3], a_addr);
        ldsm4(a[1][0], a[1][1], a[1][2], a[1][3], a_addr + 16 * 136 * 2);
#pragma unroll
        for (int g = 0; g < NI8 / 2; g++) {
            unsigned b0, b1, b2, b3;
            ldsm4t(b0, b1, b2, b3, b_addr + g * 32);
            unsigned bl[2] = {b0, b1}, bh[2] = {b2, b3};
            mma16816h(acc[0][2 * g],     a[0], bl);
            mma16816h(acc[1][2 * g],     a[1], bl);
            mma16816h(acc[0][2 * g + 1], a[0], bh);
            mma16816h(acc[1][2 * g + 1], a[1], bh);
        }
        a_addr += 32;
        b_addr += 16 * LDB * 2;
    }
}

// ---------------- kernel 0: weight prep ----------------
__global__ void prep_kernel(const float* __restrict__ qkv_w,
                            const float* __restrict__ o1_w,
                            const float* __restrict__ o2_w) {
    int idx = blockIdx.x * blockDim.x + threadIdx.x;
    int nthr = gridDim.x * blockDim.x;
    for (int i = idx; i < BATCH * HEADS * 16 * 16; i += nthr) g_kv[i] = 0.f;
    for (int i = idx; i < 256 * 128; i += nthr) {
        int r = i >> 7, c = i & 127;
        int h = r >> 5, j = r & 31;
        int src = (j < 16) ? (48 * h + 16 + j) : (48 * h + 32 + (j - 16));
        g_wkv[i] = __float2half_rn(qkv_w[src * 128 + c]);
    }
    for (int i = idx; i < 128 * 128; i += nthr) {
        g_o1h[i] = __float2half_rn(o1_w[i]);
        g_o2h[i] = __float2half_rn(o2_w[i]);
    }
}

// ---------------- kernel 1: persistent x->fp16 + k,v projection + reg-LN + reg-kv MMA ----------------
#define KVJOBS    1024
#define KVS_WT    0
#define KVS_XT    (256 * 136 * 2)
#define KVS_STAGE (KVS_XT + 128 * 136 * 2)
#define KVS_QB    (KVS_STAGE + 128 * 128 * 4)
#define KVS_SMEM  (KVS_QB + 256 * 4)

__global__ void __launch_bounds__(512, 1) kv_kernel(const float* __restrict__ x,
                                                    const float* __restrict__ qkv_b,
                                                    const float* __restrict__ kln_w,
                                                    const float* __restrict__ kln_b,
                                                    const float* __restrict__ vln_w,
                                                    const float* __restrict__ vln_b) {
    extern __shared__ char smem[];
    __half* Wt = (__half*)(smem + KVS_WT);
    __half* xt = (__half*)(smem + KVS_XT);
    float* stg = (float*)(smem + KVS_STAGE);
    float* qb = (float*)(smem + KVS_QB);

    int tid = threadIdx.x;
    int nb = gridDim.x;
    int js = (int)(((long long)blockIdx.x * KVJOBS) / nb);
    int je = (int)(((long long)(blockIdx.x + 1) * KVJOBS) / nb);
    if (js >= je) return;

    {
        unsigned wt = smem_u32(Wt);
        for (int i = tid; i < 256 * 16; i += 512) {
            int r = i >> 4, c = i & 15;
            cpasync16(wt + r * 272 + c * 16, g_wkv + r * 128 + c * 8);
        }
        int b0_ = js >> 7, n00 = (js & 127) << 7;
        const float* xsrc = x + (size_t)b0_ * CCH * NTOK + n00;
        unsigned sa = smem_u32(stg);
        for (int i = tid; i < 128 * 32; i += 512) {
            int r = i >> 5, c = i & 31;
            cpasync16(sa + r * 512 + c * 16, xsrc + (size_t)r * NTOK + c * 4);
        }
        CP_COMMIT();
    }
    if (tid < 256) {
        int h = tid >> 5, j = tid & 31;
        int src_r = (j < 16) ? (48 * h + 16 + j) : (48 * h + 32 + (j - 16));
        qb[tid] = qkv_b[src_r];
    }

    int w = tid >> 5, l = tid & 31;
    int lr = l >> 2, lc = l & 3;
    int mw = w >> 1;
    int nw = w & 1;
    int rbase = mw * 32, cbase = nw * 64;

    float lw[2][2], lb[2][2];
    lw[0][0] = kln_w[mw * 16 + lr];     lw[0][1] = kln_w[mw * 16 + lr + 8];
    lb[0][0] = kln_b[mw * 16 + lr];     lb[0][1] = kln_b[mw * 16 + lr + 8];
    lw[1][0] = vln_w[mw * 16 + lr];     lw[1][1] = vln_w[mw * 16 + lr + 8];
    lb[1][0] = vln_b[mw * 16 + lr];     lb[1][1] = vln_b[mw * 16 + lr + 8];

    float acc2[2][4];
#pragma unroll
    for (int e = 0; e < 2; e++)
#pragma unroll
        for (int q = 0; q < 4; q++) acc2[e][q] = 0.f;

    float q0 = qb[rbase + lr],      q1 = qb[rbase + lr + 8];
    float q2 = qb[rbase + 16 + lr], q3 = qb[rbase + 16 + lr + 8];

    for (int j = js; j < je; j++) {
        int b = j >> 7;
        int n0 = (j & 127) << 7;

        CP_WAIT(0);
        __syncthreads();

        __half* x16b = g_x16 + (size_t)b * CCH * NTOK;
#pragma unroll
        for (int k = 0; k < 8; k++) {
            int i = tid + k * 512;
            int r = i >> 5, c4 = i & 31;
            float4 v = *(const float4*)(stg + r * 128 + c4 * 4);
            __half2 h0 = __floats2half2_rn(v.x, v.y);
            __half2 h1 = __floats2half2_rn(v.z, v.w);
            uint2 u;
            u.x = *reinterpret_cast<unsigned*>(&h0);
            u.y = *reinterpret_cast<unsigned*>(&h1);
            *(uint2*)(xt + r * 136 + c4 * 4) = u;
            *(uint2*)(x16b + (size_t)r * NTOK + n0 + c4 * 4) = u;
        }
        __syncthreads();

        if (j + 1 < je) {
            int jn = j + 1;
            const float* xsrc = x + (size_t)(jn >> 7) * CCH * NTOK + ((jn & 127) << 7);
            unsigned sa = smem_u32(stg);
            for (int i = tid; i < 128 * 32; i += 512) {
                int r = i >> 5, c = i & 31;
                cpasync16(sa + r * 512 + c * 16, xsrc + (size_t)r * NTOK + c * 4);
            }
            CP_COMMIT();
        }

        float acc[2][8][4];
#pragma unroll
        for (int a_ = 0; a_ < 2; a_++)
#pragma unroll
            for (int b_ = 0; b_ < 8; b_++)
#pragma unroll
                for (int c_ = 0; c_ < 4; c_++) acc[a_][b_][c_] = 0.f;

        gemm_t<8, 136>(Wt, xt, acc, rbase, cbase, l);

#pragma unroll
        for (int ni = 0; ni < 8; ni++) {
            acc[0][ni][0] += q0; acc[0][ni][1] += q0;
            acc[0][ni][2] += q1; acc[0][ni][3] += q1;
            acc[1][ni][0] += q2; acc[1][ni][1] += q2;
            acc[1][ni][2] += q3; acc[1][ni][3] += q3;
        }

        unsigned kf[8][2], vf[8][2];
#pragma unroll
        for (int mi = 0; mi < 2; mi++) {
#pragma unroll
            for (int ni = 0; ni < 8; ni++) {
                float* c = acc[mi][ni];
                __half2 s2 = __floats2half2_rn(c[0] + c[2], c[1] + c[3]);
                __half2 q2h = __floats2half2_rn(fmaf(c[0], c[0], c[2] * c[2]),
                                                fmaf(c[1], c[1], c[3] * c[3]));
                unsigned su = *reinterpret_cast<unsigned*>(&s2);
                unsigned qu = *reinterpret_cast<unsigned*>(&q2h);
#pragma unroll
                for (int m = 4; m <= 16; m <<= 1) {
                    unsigned so = __shfl_xor_sync(0xffffffffu, su, m);
                    unsigned qo = __shfl_xor_sync(0xffffffffu, qu, m);
                    __half2 rs2 = __hadd2(*reinterpret_cast<__half2*>(&su),
                                          *reinterpret_cast<__half2*>(&so));
                    __half2 rq2 = __hadd2(*reinterpret_cast<__half2*>(&qu),
                                          *reinterpret_cast<__half2*>(&qo));
                    su = *reinterpret_cast<unsigned*>(&rs2);
                    qu = *reinterpret_cast<unsigned*>(&rq2);
                }
                float2 s = __half22float2(*reinterpret_cast<__half2*>(&su));
                float2 q = __half22float2(*reinterpret_cast<__half2*>(&qu));
                float ma = s.x * (1.f / 16.f);
                float va = fmaxf((q.x - 16.f * ma * ma) * (1.f / 15.f), 1e-12f);
                float rsa = rsqrt_fast(va);
                float ia = fmaf(-LN_EPS * rsa, rsa, rsa);
                float mb = s.y * (1.f / 16.f);
                float vb = fmaxf((q.y - 16.f * mb * mb) * (1.f / 15.f), 1e-12f);
                float rsb = rsqrt_fast(vb);
                float ib = fmaf(-LN_EPS * rsb, rsb, rsb);
                float n0v = lw[mi][0] * ((c[0] - ma) * ia) + lb[mi][0];
                float n1v = lw[mi][0] * ((c[1] - mb) * ib) + lb[mi][0];
                float n2v = lw[mi][1] * ((c[2] - ma) * ia) + lb[mi][1];
                float n3v = lw[mi][1] * ((c[3] - mb) * ib) + lb[mi][1];
                unsigned lo = pk2h(n0v, n1v);
                unsigned hi = pk2h(n2v, n3v);
                if (mi == 0) { kf[ni][0] = lo; kf[ni][1] = hi; }
                else         { vf[ni][0] = lo; vf[ni][1] = hi; }
            }
        }

#pragma unroll
        for (int tc = 0; tc < 4; tc++) {
            unsigned a[4] = {kf[2 * tc][0], kf[2 * tc][1], kf[2 * tc + 1][0], kf[2 * tc + 1][1]};
            unsigned b0[2] = {vf[2 * tc][0], vf[2 * tc + 1][0]};
            unsigned b1[2] = {vf[2 * tc][1], vf[2 * tc + 1][1]};
            mma16816h(acc2[0], a, b0);
            mma16816h(acc2[1], a, b1);
        }

        if (j + 1 >= je || ((j + 1) >> 7) != b) {
            float* base = g_kv + (size_t)(b * HEADS + mw) * 256;
#pragma unroll
            for (int eh = 0; eh < 2; eh++) {
                int e0 = eh * 8 + lc * 2;
                atomicAdd(base + lr * 16 + e0,           acc2[eh][0]);
                atomicAdd(base + lr * 16 + e0 + 1,       acc2[eh][1]);
                atomicAdd(base + (lr + 8) * 16 + e0,     acc2[eh][2]);
                atomicAdd(base + (lr + 8) * 16 + e0 + 1, acc2[eh][3]);
            }
#pragma unroll
            for (int e = 0; e < 2; e++)
#pragma unroll
                for (int q = 0; q < 4; q++) acc2[e][q] = 0.f;
        }
    }
}

// ---------------- kernel 2: compose g_meff = Meff_b + I, meffb (512 threads) ----------------
__global__ void compose_kernel(const float* __restrict__ qkv_w, const float* __restrict__ qkv_b) {
    __shared__ float kvs[256];
    int g = blockIdx.x, b = blockIdx.y;
    int tid = threadIdx.x;
    int ci = tid & 127;
    int eg = tid >> 7;

    if (tid < 256)
        kvs[tid] = g_kv[(b * HEADS + g) * 256 + tid] * (1.f / (float)NTOK);
    __syncthreads();

    if (tid < 16) {
        float s = 0.f;
#pragma unroll
        for (int d = 0; d < 16; d++) s += qkv_b[48 * g + d] * kvs[d * 16 + tid];
        g_meffb[b * 128 + g * 16 + tid] = s;
    }

    float wq[16];
#pragma unroll
    for (int d = 0; d < 16; d++) wq[d] = qkv_w[(48 * g + d) * 128 + ci];

    __half* mdst = g_meff + ((size_t)b * 128 + g * 16) * 128 + ci;
#pragma unroll
    for (int ee = 0; ee < 4; ee++) {
        int e = eg * 4 + ee;
        float s = 0.f;
#pragma unroll
        for (int d = 0; d < 16; d++) s += wq[d] * kvs[d * 16 + e];
        if (g * 16 + e == ci) s += 1.f;   // fold residual identity (fp32 add, then fp16 round)
        mdst[e * 128] = __float2half_rn(s);
    }
}

// ---------------- kernel 3: persistent fused main ----------------
#define NJOBS  1024
#define MP_LD  136
#define MP_T   (128 * MP_LD * 2)
#define MP_XT0 0
#define MP_XT1 (1 * MP_T)
#define MP_RT  (2 * MP_T)
#define MP_WM  (3 * MP_T)
#define MP_W1  (4 * MP_T)
#define MP_W2  (5 * MP_T)
#define MP_BIAS (6 * MP_T)
#define MP_SMEM (MP_BIAS + 3 * 128 * 4)

__global__ void __launch_bounds__(512, 1) main_kernel(const float* __restrict__ o1_b,
                                                      const float* __restrict__ o2_b,
                                                      float* __restrict__ out) {
    extern __shared__ char smem[];
    __half* xtb[2] = {(__half*)(smem + MP_XT0), (__half*)(smem + MP_XT1)};
    __half* rt = (__half*)(smem + MP_RT);
    __half* wM = (__half*)(smem + MP_WM);
    __half* w1 = (__half*)(smem + MP_W1);
    __half* w2 = (__half*)(smem + MP_W2);
    float* bias = (float*)(smem + MP_BIAS);

    int tid = threadIdx.x;
    int nb = gridDim.x;
    int js = (int)(((long long)blockIdx.x * NJOBS) / nb);
    int je = (int)(((long long)(blockIdx.x + 1) * NJOBS) / nb);
    if (js >= je) return;

    {
        unsigned a1 = smem_u32(w1), a2 = smem_u32(w2);
        for (int i = tid; i < 128 * 16; i += 512) {
            int r = i >> 4, c = i & 15;
            cpasync16(a1 + r * 272 + c * 16, g_o1h + r * 128 + c * 8);
            cpasync16(a2 + r * 272 + c * 16, g_o2h + r * 128 + c * 8);
        }
        int b0_ = js >> 7, n00 = (js & 127) << 7;
        const __half* xsrc = g_x16 + (size_t)b0_ * CCH * NTOK + n00;
        unsigned xa = smem_u32(xtb[0]);
        for (int i = tid; i < 128 * 16; i += 512) {
            int r = i >> 4, c = i & 15;
            cpasync16(xa + r * 272 + c * 16, xsrc + (size_t)r * NTOK + c * 8);
        }
        CP_COMMIT();
    }
    if (tid < 128) {
        bias[128 + tid] = o1_b[tid];
        bias[256 + tid] = o2_b[tid];
    }

    int w = tid >> 5, l = tid & 31;
    int lr = l >> 2, lc = l & 3;
    int mw = w >> 2, nw = w & 3;
    int rbase = mw * 32, cbase = nw * 32;

    int cur_b = -1;
    int buf = 0;

    for (int j = js; j < je; j++) {
        int b = j >> 7;
        int n0 = (j & 127) << 7;

        if (j + 1 < je) {
            int jn = j + 1;
            const __half* xsrc = g_x16 + (size_t)(jn >> 7) * CCH * NTOK + ((jn & 127) << 7);
            unsigned xa = smem_u32(xtb[buf ^ 1]);
            for (int i = tid; i < 128 * 16; i += 512) {
                int r = i >> 4, c = i & 15;
                cpasync16(xa + r * 272 + c * 16, xsrc + (size_t)r * NTOK + c * 8);
            }
        }
        CP_COMMIT();

        if (b != cur_b) {
            if (tid < 128) bias[tid] = g_meffb[b * 128 + tid];
            unsigned wa = smem_u32(wM);
            const __half* msrc = g_meff + (size_t)b * 128 * 128;
            for (int i = tid; i < 128 * 16; i += 512) {
                int r = i >> 4, c = i & 15;
                cpasync16(wa + r * 272 + c * 16, msrc + r * 128 + c * 8);
            }
            CP_COMMIT();
            CP_WAIT(0);
            cur_b = b;
        } else {
            CP_WAIT(1);
        }
        __syncthreads();

        const __half* xt = xtb[buf];
        float acc[2][4][4];
#define ZACC4() { _Pragma("unroll") for (int a_=0;a_<2;a_++) _Pragma("unroll") for (int b_=0;b_<4;b_++) _Pragma("unroll") for (int c_=0;c_<4;c_++) acc[a_][b_][c_]=0.f; }

        // ---- phase 1: rt = (Meff+I)*x + meffb  (identity folded into weights) ----
        ZACC4();
        gemm_t<4, MP_LD>(wM, xt, acc, rbase, cbase, l);
        {
            float bm0 = bias[rbase + lr],      bm1 = bias[rbase + lr + 8];
            float bm2 = bias[rbase + 16 + lr], bm3 = bias[rbase + 16 + lr + 8];
#pragma unroll
            for (int mi = 0; mi < 2; mi++) {
                int row = rbase + mi * 16 + lr;
                float ba0 = mi ? bm2 : bm0, ba1 = mi ? bm3 : bm1;
#pragma unroll
                for (int ni = 0; ni < 4; ni++) {
                    int col = cbase + ni * 8 + lc * 2;
                    *(unsigned*)(rt + row * MP_LD + col) =
                        pk2h(acc[mi][ni][0] + ba0, acc[mi][ni][1] + ba0);
                    *(unsigned*)(rt + (row + 8) * MP_LD + col) =
                        pk2h(acc[mi][ni][2] + ba1, acc[mi][ni][3] + ba1);
                }
            }
        }
        __syncthreads();

        // ---- phase 2: h1 = gelu(o1 * rt + b1) ----
        ZACC4();
        gemm_t<4, MP_LD>(w1, rt, acc, rbase, cbase, l);
        {
            float b10 = bias[128 + rbase + lr],      b11 = bias[128 + rbase + lr + 8];
            float b12 = bias[128 + rbase + 16 + lr], b13 = bias[128 + rbase + 16 + lr + 8];
#pragma unroll
            for (int mi = 0; mi < 2; mi++) {
                float ba0 = mi ? b12 : b10, ba1 = mi ? b13 : b11;
#pragma unroll
                for (int ni = 0; ni < 4; ni++) {
#pragma unroll
                    for (int q = 0; q < 4; q++) {
                        float h = acc[mi][ni][q] + ((q < 2) ? ba0 : ba1);
                        acc[mi][ni][q] = 0.5f * h * (1.f + fast_erf(h * 0.70710678118654752f));
                    }
                }
            }
        }
        __syncthreads();
#pragma unroll
        for (int mi = 0; mi < 2; mi++) {
            int row = rbase + mi * 16 + lr;
#pragma unroll
            for (int ni = 0; ni < 4; ni++) {
                int col = cbase + ni * 8 + lc * 2;
                *(unsigned*)(rt + row * MP_LD + col)       = pk2h(acc[mi][ni][0], acc[mi][ni][1]);
                *(unsigned*)(rt + (row + 8) * MP_LD + col) = pk2h(acc[mi][ni][2], acc[mi][ni][3]);
            }
        }
        __syncthreads();

        // ---- phase 3: out = o2 * h1 + b2 + x ----
        ZACC4();
        gemm_t<4, MP_LD>(w2, rt, acc, rbase, cbase, l);
        {
            float b20 = bias[256 + rbase + lr],      b21 = bias[256 + rbase + lr + 8];
            float b22 = bias[256 + rbase + 16 + lr], b23 = bias[256 + rbase + 16 + lr + 8];
            float* ob = out + (size_t)b * CCH * NTOK + n0;
#pragma unroll
            for (int mi = 0; mi < 2; mi++) {
                int row = rbase + mi * 16 + lr;
                float ba0 = mi ? b22 : b20, ba1 = mi ? b23 : b21;
#pragma unroll
                for (int ni = 0; ni < 4; ni++) {
                    int col = cbase + ni * 8 + lc * 2;
                    __half2 xv0 = *(const __half2*)(xt + row * MP_LD + col);
                    __half2 xv1 = *(const __half2*)(xt + (row + 8) * MP_LD + col);
                    float2 f0 = __half22float2(xv0), f1 = __half22float2(xv1);
                    float2 o0, o1v;
                    o0.x = acc[mi][ni][0] + ba0 + f0.x;
                    o0.y = acc[mi][ni][1] + ba0 + f0.y;
                    o1v.x = acc[mi][ni][2] + ba1 + f1.x;
                    o1v.y = acc[mi][ni][3] + ba1 + f1.y;
                    __stcs((float2*)(ob + (size_t)row * NTOK + col), o0);
                    __stcs((float2*)(ob + (size_t)(row + 8) * NTOK + col), o1v);
                }
            }
        }
        __syncthreads();   // fence xt reads before next prefetch overwrites
        buf ^= 1;
    }
}

// ---------------- launch ----------------
extern "C" void kernel_launch(void* const* d_in, const int* in_sizes, int n_in,
                              void* d_out, int out_size) {
    const float* x     = (const float*)d_in[0];
    const float* qkv_w = (const float*)d_in[1];
    const float* qkv_b = (const float*)d_in[2];
    const float* o1_w  = (const float*)d_in[3];
    const float* o1_b  = (const float*)d_in[4];
    const float* o2_w  = (const float*)d_in[5];
    const float* o2_b  = (const float*)d_in[6];
    const float* kln_w = (const float*)d_in[7];
    const float* kln_b = (const float*)d_in[8];
    const float* vln_w = (const float*)d_in[9];
    const float* vln_b = (const float*)d_in[10];
    float* out = (float*)d_out;

    cudaFuncSetAttribute(kv_kernel, cudaFuncAttributeMaxDynamicSharedMemorySize, KVS_SMEM);
    cudaFuncSetAttribute(main_kernel, cudaFuncAttributeMaxDynamicSharedMemorySize, MP_SMEM);

    int dev = 0;
    cudaGetDevice(&dev);
    int nsm = 148;
    cudaDeviceGetAttribute(&nsm, cudaDevAttrMultiProcessorCount, dev);
    if (nsm < 1) nsm = 1;
    int nkv = nsm > KVJOBS ? KVJOBS : nsm;
    int nmn = nsm > NJOBS ? NJOBS : nsm;

    prep_kernel<<<128, 256>>>(qkv_w, o1_w, o2_w);

    kv_kernel<<<nkv, 512, KVS_SMEM>>>(x, qkv_b, kln_w, kln_b, vln_w, vln_b);

    dim3 gc(HEADS, BATCH);
    compose_kernel<<<gc, 512>>>(qkv_w, qkv_b);

    main_kernel<<<nmn, 512, MP_SMEM>>>(o1_b, o2_b, out);
}